// round 5
// baseline (speedup 1.0000x reference)
#include <cuda_runtime.h>

#define NH 4
#define DIMC 128
#define HD 32
#define BT_N 2209   // (2*WS + 2*HS - 1)^2 = 47^2

typedef unsigned long long ull;

// totals: 128 windows (B=2 * 8 * 8), 256 q/window, 1024 kv/window
__device__ __align__(16) float g_Q [128 * 256  * DIMC];   // 16.8 MB
__device__ __align__(16) float g_K [128 * 1024 * DIMC];   // 67 MB
__device__ __align__(16) float g_V [128 * 1024 * DIMC];   // 67 MB
__device__ __align__(16) float g_AO[128 * 256  * DIMC];   // 16.8 MB

// ---- packed f32x2 helpers ----
__device__ __forceinline__ ull pack2(float lo, float hi) {
    ull r; asm("mov.b64 %0,{%1,%2};" : "=l"(r) : "f"(lo), "f"(hi)); return r;
}
__device__ __forceinline__ ull fma2(ull a, ull b, ull c) {
    ull d; asm("fma.rn.f32x2 %0,%1,%2,%3;" : "=l"(d) : "l"(a), "l"(b), "l"(c)); return d;
}
__device__ __forceinline__ ull add2(ull a, ull b) {
    ull d; asm("add.rn.f32x2 %0,%1,%2;" : "=l"(d) : "l"(a), "l"(b)); return d;
}
__device__ __forceinline__ ull mul2(ull a, ull b) {
    ull d; asm("mul.rn.f32x2 %0,%1,%2;" : "=l"(d) : "l"(a), "l"(b)); return d;
}
__device__ __forceinline__ float2 unpk2(ull v) {
    float2 f; asm("mov.b64 {%0,%1},%2;" : "=f"(f.x), "=f"(f.y) : "l"(v)); return f;
}
__device__ __forceinline__ float ex2f(float x) {
    float r; asm("ex2.approx.f32 %0,%1;" : "=f"(r) : "f"(x)); return r;
}

__device__ __forceinline__ int reflect_idx(int p, int n) {
    if (p < 0) p = -p;
    else if (p >= n) p = 2 * n - 2 - p;
    return p;
}

// ---------------------------------------------------------------------------
// Shared packed-GEMM pieces (unchanged — passing).
// ---------------------------------------------------------------------------
#define GEMM_SMEM_BYTES (64 * 128 * 4 + 64 * 133 * 8)   // 100864

__device__ __forceinline__ void load_wsp(ull* wsp, const float* __restrict__ W, int t) {
    #pragma unroll
    for (int it = 0; it < 32; it++) {
        int e  = t + it * 256;     // 0..8191
        int c  = e >> 6;           // 0..127
        int kp = e & 63;           // 0..63
        float2 wv = ((const float2*)W)[c * 64 + kp];   // coalesced
        wsp[kp * 133 + c] = pack2(wv.x, wv.y);
    }
}

__device__ __forceinline__ void gemm_core(const float* xs, const ull* wsp,
                                          int c0, int r0, ull accp[8][4]) {
    #pragma unroll
    for (int r = 0; r < 8; r++)
        #pragma unroll
        for (int m = 0; m < 4; m++) accp[r][m] = 0ull;

    for (int kp = 0; kp < 64; kp += 2) {
        ulonglong2 xu[8];
        #pragma unroll
        for (int r = 0; r < 8; r++)
            xu[r] = *(const ulonglong2*)(xs + (r0 + r) * 128 + kp * 2);
        #pragma unroll
        for (int m = 0; m < 4; m++) {
            ull w0 = wsp[kp * 133 + c0 + m * 32];
            ull w1 = wsp[(kp + 1) * 133 + c0 + m * 32];
            #pragma unroll
            for (int r = 0; r < 8; r++) {
                accp[r][m] = fma2(xu[r].x, w0, accp[r][m]);
                accp[r][m] = fma2(xu[r].y, w1, accp[r][m]);
            }
        }
    }
}

// ---------------------------------------------------------------------------
// proj_q
// ---------------------------------------------------------------------------
__global__ __launch_bounds__(256) void proj_q_kernel(
    const float* __restrict__ x, const float* __restrict__ Wq,
    const float* __restrict__ bq, const int* __restrict__ shift_p)
{
    extern __shared__ char smraw[];
    float* xs = (float*)smraw;
    ull*  wsp = (ull*)(smraw + 64 * 128 * 4);
    const int t = threadIdx.x;
    const int s = *shift_p;
    const long R0 = (long)blockIdx.x * 64;

    #pragma unroll
    for (int it = 0; it < 8; it++) {
        int e  = t + it * 256;
        int r  = e >> 5;
        int c4 = e & 31;
        long R = R0 + r;
        int w  = (int)(R >> 8); int qi = (int)(R & 255);
        int b  = w >> 6, wi = (w >> 3) & 7, wj = w & 7;
        int ii = qi >> 4, jj = qi & 15;
        int hh = (wi * 16 + ii + s) & 127;
        int ww = (wj * 16 + jj + s) & 127;
        ((float4*)xs)[e] =
            ((const float4*)x)[(((long)b * 128 + hh) * 128 + ww) * 32 + c4];
    }
    load_wsp(wsp, Wq, t);
    __syncthreads();

    const int c0 = t & 31;
    const int r0 = (t >> 5) * 8;
    ull accp[8][4];
    gemm_core(xs, wsp, c0, r0, accp);

    #pragma unroll
    for (int m = 0; m < 4; m++) {
        int c = c0 + m * 32;
        float bias = bq[c];
        #pragma unroll
        for (int r = 0; r < 8; r++) {
            float2 f = unpk2(accp[r][m]);
            g_Q[(R0 + r0 + r) * 128 + c] = f.x + f.y + bias;
        }
    }
}

// ---------------------------------------------------------------------------
// proj_kv
// ---------------------------------------------------------------------------
__global__ __launch_bounds__(256) void proj_kv_kernel(
    const float* __restrict__ x,
    const float* __restrict__ Wk, const float* __restrict__ bk,
    const float* __restrict__ Wv, const float* __restrict__ bv,
    const int* __restrict__ shift_p)
{
    extern __shared__ char smraw[];
    float* xs = (float*)smraw;
    ull*  wsp = (ull*)(smraw + 64 * 128 * 4);
    const int t = threadIdx.x;
    const int s = *shift_p;
    const long R0 = (long)blockIdx.x * 64;

    #pragma unroll
    for (int it = 0; it < 8; it++) {
        int e  = t + it * 256;
        int r  = e >> 5;
        int c4 = e & 31;
        long R = R0 + r;
        int w = (int)(R >> 10); int p = (int)(R & 1023);
        int u = p >> 5, v = p & 31;
        int b = w >> 6, wi = (w >> 3) & 7, wj = w & 7;
        int rh = reflect_idx(wi * 16 + u - 8, 128);
        int rw = reflect_idx(wj * 16 + v - 8, 128);
        rh = (rh + s) & 127;
        rw = (rw + s) & 127;
        ((float4*)xs)[e] =
            ((const float4*)x)[(((long)b * 128 + rh) * 128 + rw) * 32 + c4];
    }

    const int c0 = t & 31;
    const int r0 = (t >> 5) * 8;
    #pragma unroll 1
    for (int pass = 0; pass < 2; pass++) {
        const float* W  = pass ? Wv : Wk;
        const float* bb = pass ? bv : bk;
        float* g        = pass ? g_V : g_K;
        __syncthreads();
        load_wsp(wsp, W, t);
        __syncthreads();

        ull accp[8][4];
        gemm_core(xs, wsp, c0, r0, accp);

        #pragma unroll
        for (int m = 0; m < 4; m++) {
            int c = c0 + m * 32;
            float bias = bb[c];
            #pragma unroll
            for (int r = 0; r < 8; r++) {
                float2 f = unpk2(accp[r][m]);
                g[(R0 + r0 + r) * 128 + c] = f.x + f.y + bias;
            }
        }
    }
}

// ---------------------------------------------------------------------------
// attention v2: CTA = (window, head), 512 threads.
// thread = (query qi = t>>1, dim-half par = t&1): 16-dim q slice + 16-dim o
// accumulator per thread (32 regs state) -> __launch_bounds__(512,2) gives
// 32 warps/SM (2x round-4). Pair halves combined with one shfl.bfly per key.
// Fixed-max softmax, constants folded (single ex2/key).
// ---------------------------------------------------------------------------
__global__ __launch_bounds__(512, 2) void attn_kernel(const float* __restrict__ bias_table)
{
    __shared__ __align__(16) float bias_s[BT_N + 3];
    __shared__ __align__(16) float ks[64 * 32];
    __shared__ __align__(16) float vs[64 * 32];
    const int t   = threadIdx.x;
    const int qi  = t >> 1;
    const int par = t & 1;
    const int w = blockIdx.x;
    const int h = blockIdx.y;
    const float LOG2E = 1.4426950408889634f;

    for (int i = t; i < BT_N; i += 512) bias_s[i] = bias_table[i * NH + h] * LOG2E;

    // q slice: 16 floats at h*32 + par*16, pre-scaled by scale*log2e
    ull qp[8];
    {
        const float qs = 0.17677669529663687f * LOG2E;
        const float4* qsrc = (const float4*)(g_Q + ((long)(w * 256 + qi)) * 128 + h * 32 + par * 16);
        #pragma unroll
        for (int i = 0; i < 4; i++) {
            float4 v4 = qsrc[i];
            qp[2 * i]     = pack2(v4.x * qs, v4.y * qs);
            qp[2 * i + 1] = pack2(v4.z * qs, v4.w * qs);
        }
    }
    // bias: idx = qoff - ck*47 - dk; wrap negatives by +2209 (JAX gather)
    const int qoff = ((qi >> 5) + 31) * 47 + (qi & 31) + 23;

    float l0 = 0.f, l1 = 0.f;
    ull op[8];
    #pragma unroll
    for (int i = 0; i < 8; i++) op[i] = 0ull;

    const int slice = par * 16;   // float offset of this thread's dim-half

    for (int kt = 0; kt < 16; kt++) {
        __syncthreads();
        {
            const float4* Ksrc = (const float4*)(g_K + ((long)w * 1024 + kt * 64) * 128 + h * 32);
            const float4* Vsrc = (const float4*)(g_V + ((long)w * 1024 + kt * 64) * 128 + h * 32);
            int key = t >> 3, c4 = t & 7;     // 512 threads = 64 rows x 8 float4
            ((float4*)ks)[t] = Ksrc[key * 32 + c4];
            ((float4*)vs)[t] = Vsrc[key * 32 + c4];
        }
        __syncthreads();

        #pragma unroll 1
        for (int half = 0; half < 2; half++) {
            const int ck    = kt * 2 + half;
            const int ibase = qoff - ck * 47;
            const ulonglong2* kb = (const ulonglong2*)(ks + half * 1024 + slice);
            const ulonglong2* vb = (const ulonglong2*)(vs + half * 1024 + slice);
            #pragma unroll 2
            for (int dk = 0; dk < 32; dk++) {
                const ulonglong2* kr = kb + dk * 8;   // row stride 32 floats
                ulonglong2 ka = kr[0], kc = kr[1], ke = kr[2], kg = kr[3];
                ull a0 = fma2(qp[0], ka.x, 0ull);
                ull a1 = fma2(qp[1], ka.y, 0ull);
                ull a2 = fma2(qp[2], kc.x, 0ull);
                ull a3 = fma2(qp[3], kc.y, 0ull);
                a0 = fma2(qp[4], ke.x, a0);
                a1 = fma2(qp[5], ke.y, a1);
                a2 = fma2(qp[6], kg.x, a2);
                a3 = fma2(qp[7], kg.y, a3);
                float2 f = unpk2(add2(add2(a0, a1), add2(a2, a3)));
                float sh = f.x + f.y;
                float st = sh + __shfl_xor_sync(0xffffffffu, sh, 1);

                int idx = ibase - dk;
                if (idx < 0) idx += BT_N;
                float pe = ex2f(st + bias_s[idx]);
                if (dk & 1) l1 += pe; else l0 += pe;

                ull pp = pack2(pe, pe);
                const ulonglong2* vr = vb + dk * 8;
                ulonglong2 va = vr[0], vc = vr[1], ve = vr[2], vg = vr[3];
                op[0] = fma2(va.x, pp, op[0]);
                op[1] = fma2(va.y, pp, op[1]);
                op[2] = fma2(vc.x, pp, op[2]);
                op[3] = fma2(vc.y, pp, op[3]);
                op[4] = fma2(ve.x, pp, op[4]);
                op[5] = fma2(ve.y, pp, op[5]);
                op[6] = fma2(vg.x, pp, op[6]);
                op[7] = fma2(vg.y, pp, op[7]);
            }
        }
    }

    const float inv = 1.f / (l0 + l1);
    const ull invp = pack2(inv, inv);
    ulonglong2* dst = (ulonglong2*)(g_AO + ((long)(w * 256 + qi)) * 128 + h * 32 + slice);
    #pragma unroll
    for (int i = 0; i < 4; i++) {
        ulonglong2 v;
        v.x = mul2(op[2 * i], invp);
        v.y = mul2(op[2 * i + 1], invp);
        dst[i] = v;
    }
}

// ---------------------------------------------------------------------------
// out_proj
// ---------------------------------------------------------------------------
__global__ __launch_bounds__(256) void out_proj_kernel(
    const float* __restrict__ Wp, const float* __restrict__ bp,
    const int* __restrict__ shift_p, float* __restrict__ out)
{
    extern __shared__ char smraw[];
    float* xs = (float*)smraw;
    ull*  wsp = (ull*)(smraw + 64 * 128 * 4);
    const int t = threadIdx.x;
    const int s = *shift_p;
    const long R0 = (long)blockIdx.x * 64;

    #pragma unroll
    for (int it = 0; it < 8; it++) {
        int e = t + it * 256;
        ((float4*)xs)[e] = ((const float4*)g_AO)[R0 * 32 + e];
    }
    load_wsp(wsp, Wp, t);
    __syncthreads();

    const int c0 = t & 31;
    const int r0 = (t >> 5) * 8;
    ull accp[8][4];
    gemm_core(xs, wsp, c0, r0, accp);

    #pragma unroll
    for (int r = 0; r < 8; r++) {
        long R = R0 + r0 + r;
        int w  = (int)(R >> 8); int qi = (int)(R & 255);
        int b  = w >> 6, wi = (w >> 3) & 7, wj = w & 7;
        int ii = qi >> 4, jj = qi & 15;
        int oh = (wi * 16 + ii + s) & 127;
        int ow = (wj * 16 + jj + s) & 127;
        float* drow = out + (((long)b * 128 + oh) * 128 + ow) * 128;
        #pragma unroll
        for (int m = 0; m < 4; m++) {
            int c = c0 + m * 32;
            float2 f = unpk2(accp[r][m]);
            drow[c] = f.x + f.y + bp[c];
        }
    }
}

// ---------------------------------------------------------------------------
extern "C" void kernel_launch(void* const* d_in, const int* in_sizes, int n_in,
                              void* d_out, int out_size)
{
    const float* x  = (const float*)d_in[0];
    const float* Wq = (const float*)d_in[1];
    const float* bq = (const float*)d_in[2];
    const float* Wk = (const float*)d_in[3];
    const float* bk = (const float*)d_in[4];
    const float* Wv = (const float*)d_in[5];
    const float* bv = (const float*)d_in[6];
    const float* Wp = (const float*)d_in[7];
    const float* bp = (const float*)d_in[8];
    const float* bt = (const float*)d_in[9];
    const int* shift = (const int*)d_in[10];
    float* out = (float*)d_out;

    const size_t smem = GEMM_SMEM_BYTES;   // 100864 B
    cudaFuncSetAttribute(proj_q_kernel,   cudaFuncAttributeMaxDynamicSharedMemorySize, (int)smem);
    cudaFuncSetAttribute(proj_kv_kernel,  cudaFuncAttributeMaxDynamicSharedMemorySize, (int)smem);
    cudaFuncSetAttribute(out_proj_kernel, cudaFuncAttributeMaxDynamicSharedMemorySize, (int)smem);

    proj_q_kernel  <<<512,  256, smem>>>(x, Wq, bq, shift);
    proj_kv_kernel <<<2048, 256, smem>>>(x, Wk, bk, Wv, bv, shift);
    attn_kernel    <<<dim3(128, 4), 512>>>(bt);
    out_proj_kernel<<<512,  256, smem>>>(Wp, bp, shift, out);
}

// round 6
// speedup vs baseline: 1.2820x; 1.2820x over previous
#include <cuda_runtime.h>

#define NH 4
#define DIMC 128
#define HD 32
#define BT_N 2209   // (2*WS + 2*HS - 1)^2 = 47^2

typedef unsigned long long ull;

// Per-PIXEL layouts (rolled space): 32768 rows x 128. 16.8 MB each.
__device__ __align__(16) float g_Q [32768 * DIMC];
__device__ __align__(16) float g_K [32768 * DIMC];
__device__ __align__(16) float g_V [32768 * DIMC];
__device__ __align__(16) float g_AO[32768 * DIMC];

// ---- packed f32x2 helpers ----
__device__ __forceinline__ ull pack2(float lo, float hi) {
    ull r; asm("mov.b64 %0,{%1,%2};" : "=l"(r) : "f"(lo), "f"(hi)); return r;
}
__device__ __forceinline__ ull fma2(ull a, ull b, ull c) {
    ull d; asm("fma.rn.f32x2 %0,%1,%2,%3;" : "=l"(d) : "l"(a), "l"(b), "l"(c)); return d;
}
__device__ __forceinline__ ull add2(ull a, ull b) {
    ull d; asm("add.rn.f32x2 %0,%1,%2;" : "=l"(d) : "l"(a), "l"(b)); return d;
}
__device__ __forceinline__ ull mul2(ull a, ull b) {
    ull d; asm("mul.rn.f32x2 %0,%1,%2;" : "=l"(d) : "l"(a), "l"(b)); return d;
}
__device__ __forceinline__ float2 unpk2(ull v) {
    float2 f; asm("mov.b64 {%0,%1},%2;" : "=f"(f.x), "=f"(f.y) : "l"(v)); return f;
}
__device__ __forceinline__ float ex2f(float x) {
    float r; asm("ex2.approx.f32 %0,%1;" : "=f"(r) : "f"(x)); return r;
}

__device__ __forceinline__ int reflect_idx(int p, int n) {
    if (p < 0) p = -p;
    else if (p >= n) p = 2 * n - 2 - p;
    return p;
}

// ---------------------------------------------------------------------------
// Shared packed-GEMM pieces (unchanged — passing since round 3).
// ---------------------------------------------------------------------------
#define GEMM_SMEM_BYTES (64 * 128 * 4 + 64 * 133 * 8)   // 100864

__device__ __forceinline__ void load_wsp(ull* wsp, const float* __restrict__ W, int t) {
    #pragma unroll
    for (int it = 0; it < 32; it++) {
        int e  = t + it * 256;     // 0..8191
        int c  = e >> 6;           // 0..127
        int kp = e & 63;           // 0..63
        float2 wv = ((const float2*)W)[c * 64 + kp];   // coalesced
        wsp[kp * 133 + c] = pack2(wv.x, wv.y);
    }
}

__device__ __forceinline__ void gemm_core(const float* xs, const ull* wsp,
                                          int c0, int r0, ull accp[8][4]) {
    #pragma unroll
    for (int r = 0; r < 8; r++)
        #pragma unroll
        for (int m = 0; m < 4; m++) accp[r][m] = 0ull;

    for (int kp = 0; kp < 64; kp += 2) {
        ulonglong2 xu[8];
        #pragma unroll
        for (int r = 0; r < 8; r++)
            xu[r] = *(const ulonglong2*)(xs + (r0 + r) * 128 + kp * 2);
        #pragma unroll
        for (int m = 0; m < 4; m++) {
            ull w0 = wsp[kp * 133 + c0 + m * 32];
            ull w1 = wsp[(kp + 1) * 133 + c0 + m * 32];
            #pragma unroll
            for (int r = 0; r < 8; r++) {
                accp[r][m] = fma2(xu[r].x, w0, accp[r][m]);
                accp[r][m] = fma2(xu[r].y, w1, accp[r][m]);
            }
        }
    }
}

// ---------------------------------------------------------------------------
// proj_qkv: per-pixel Q,K,V = x @ W^T + b  (one x gather, three weight passes)
// Rows are pixels in rolled space: R = (b, r1, r2); x read at ((r1+s)&127,(r2+s)&127).
// ---------------------------------------------------------------------------
__global__ __launch_bounds__(256) void proj_qkv_kernel(
    const float* __restrict__ x,
    const float* __restrict__ Wq, const float* __restrict__ bq,
    const float* __restrict__ Wk, const float* __restrict__ bk,
    const float* __restrict__ Wv, const float* __restrict__ bv,
    const int* __restrict__ shift_p)
{
    extern __shared__ char smraw[];
    float* xs = (float*)smraw;
    ull*  wsp = (ull*)(smraw + 64 * 128 * 4);
    const int t = threadIdx.x;
    const int s = *shift_p;
    const long R0 = (long)blockIdx.x * 64;

    #pragma unroll
    for (int it = 0; it < 8; it++) {
        int e  = t + it * 256;
        int r  = e >> 5;
        int c4 = e & 31;
        long R = R0 + r;
        int b  = (int)(R >> 14);
        int r1 = (int)(R >> 7) & 127;
        int r2 = (int)R & 127;
        int hh = (r1 + s) & 127;
        int ww = (r2 + s) & 127;
        ((float4*)xs)[e] =
            ((const float4*)x)[(((long)b * 128 + hh) * 128 + ww) * 32 + c4];
    }

    const int c0 = t & 31;
    const int r0 = (t >> 5) * 8;
    #pragma unroll 1
    for (int pass = 0; pass < 3; pass++) {
        const float* W  = pass == 0 ? Wq : (pass == 1 ? Wk : Wv);
        const float* bb = pass == 0 ? bq : (pass == 1 ? bk : bv);
        float* g        = pass == 0 ? g_Q : (pass == 1 ? g_K : g_V);
        __syncthreads();                    // xs ready / prior wsp reads done
        load_wsp(wsp, W, t);
        __syncthreads();

        ull accp[8][4];
        gemm_core(xs, wsp, c0, r0, accp);

        #pragma unroll
        for (int m = 0; m < 4; m++) {
            int c = c0 + m * 32;
            float bias = bb[c];
            #pragma unroll
            for (int r = 0; r < 8; r++) {
                float2 f = unpk2(accp[r][m]);
                g[(R0 + r0 + r) * 128 + c] = f.x + f.y + bias;
            }
        }
    }
}

// ---------------------------------------------------------------------------
// attention: round-4 winner core (one CTA per (window, head), 256 threads,
// one query per thread, broadcast K/V tiles, fixed-max softmax, single ex2).
// K/V now gathered from per-pixel layout via reflect-index tables in smem.
// ---------------------------------------------------------------------------
__global__ __launch_bounds__(256) void attn_kernel(const float* __restrict__ bias_table)
{
    __shared__ __align__(16) float bias_s[BT_N + 3];
    __shared__ __align__(16) float ks[64 * 32];
    __shared__ __align__(16) float vs[64 * 32];
    __shared__ int rhs[32], rws[32];
    const int t = threadIdx.x;
    const int w = blockIdx.x;
    const int h = blockIdx.y;
    const int b  = w >> 6, wi = (w >> 3) & 7, wj = w & 7;
    const float LOG2E = 1.4426950408889634f;

    if (t < 32)            rhs[t]      = reflect_idx(wi * 16 + t - 8, 128);
    else if (t < 64)       rws[t - 32] = reflect_idx(wj * 16 + (t - 32) - 8, 128);

    for (int i = t; i < BT_N; i += 256) bias_s[i] = bias_table[i * NH + h] * LOG2E;

    // q row: pixel (b, wi*16+ii, wj*16+jj), pre-scaled by scale*log2e
    ull qp[16];
    {
        const float qs = 0.17677669529663687f * LOG2E;
        const int ii = t >> 4, jj = t & 15;
        const long qrow = ((long)b * 128 + wi * 16 + ii) * 128 + wj * 16 + jj;
        const float4* qsrc = (const float4*)(g_Q + qrow * 128 + h * 32);
        #pragma unroll
        for (int i = 0; i < 8; i++) {
            float4 v4 = qsrc[i];
            qp[2 * i]     = pack2(v4.x * qs, v4.y * qs);
            qp[2 * i + 1] = pack2(v4.z * qs, v4.w * qs);
        }
    }
    // bias: idx = qoff - ck*47 - dk; wrap negatives by +2209 (JAX gather)
    const int qoff = ((t >> 5) + 31) * 47 + (t & 31) + 23;

    float lacc[4] = {0.f, 0.f, 0.f, 0.f};
    ull op[16];
    #pragma unroll
    for (int i = 0; i < 16; i++) op[i] = 0ull;

    for (int kt = 0; kt < 16; kt++) {
        __syncthreads();
        {
            int e = t;
            #pragma unroll
            for (int it = 0; it < 2; it++, e += 256) {
                int key = e >> 3, c4 = e & 7;
                int u = kt * 2 + (key >> 5);
                int v = key & 31;
                long krow = ((long)b * 128 + rhs[u]) * 128 + rws[v];
                ((float4*)ks)[e] = ((const float4*)(g_K + krow * 128 + h * 32))[c4];
                ((float4*)vs)[e] = ((const float4*)(g_V + krow * 128 + h * 32))[c4];
            }
        }
        __syncthreads();

        #pragma unroll 1
        for (int half = 0; half < 2; half++) {
            const int ck    = kt * 2 + half;
            const int ibase = qoff - ck * 47;
            const float* ksh = ks + half * 32 * 32;
            const float* vsh = vs + half * 32 * 32;
            #pragma unroll 4
            for (int dk = 0; dk < 32; dk++) {
                const ulonglong2* kr = (const ulonglong2*)(ksh + dk * 32);
                ull a0 = 0ull, a1 = 0ull, a2 = 0ull, a3 = 0ull;
                #pragma unroll
                for (int i = 0; i < 4; i++) {
                    ulonglong2 k01 = kr[2 * i];
                    ulonglong2 k23 = kr[2 * i + 1];
                    a0 = fma2(qp[4 * i + 0], k01.x, a0);
                    a1 = fma2(qp[4 * i + 1], k01.y, a1);
                    a2 = fma2(qp[4 * i + 2], k23.x, a2);
                    a3 = fma2(qp[4 * i + 3], k23.y, a3);
                }
                float2 f = unpk2(add2(add2(a0, a1), add2(a2, a3)));
                int idx = ibase - dk;
                if (idx < 0) idx += BT_N;
                float p = ex2f(f.x + f.y + bias_s[idx]);
                lacc[dk & 3] += p;

                ull pp = pack2(p, p);
                const ulonglong2* vr = (const ulonglong2*)(vsh + dk * 32);
                #pragma unroll
                for (int i = 0; i < 8; i++) {
                    ulonglong2 vv = vr[i];
                    op[2 * i]     = fma2(vv.x, pp, op[2 * i]);
                    op[2 * i + 1] = fma2(vv.y, pp, op[2 * i + 1]);
                }
            }
        }
    }

    const float inv = 1.f / ((lacc[0] + lacc[1]) + (lacc[2] + lacc[3]));
    const ull invp = pack2(inv, inv);
    // write o to pixel-ordered g_AO
    const int ii = t >> 4, jj = t & 15;
    const long orow = ((long)b * 128 + wi * 16 + ii) * 128 + wj * 16 + jj;
    ulonglong2* dst = (ulonglong2*)(g_AO + orow * 128 + h * 32);
    #pragma unroll
    for (int i = 0; i < 8; i++) {
        ulonglong2 v;
        v.x = mul2(op[2 * i], invp);
        v.y = mul2(op[2 * i + 1], invp);
        dst[i] = v;
    }
}

// ---------------------------------------------------------------------------
// out_proj: out = AO @ Wp^T + bp; AO rows are pixels (contiguous read),
// scatter applies the +s roll.
// ---------------------------------------------------------------------------
__global__ __launch_bounds__(256) void out_proj_kernel(
    const float* __restrict__ Wp, const float* __restrict__ bp,
    const int* __restrict__ shift_p, float* __restrict__ out)
{
    extern __shared__ char smraw[];
    float* xs = (float*)smraw;
    ull*  wsp = (ull*)(smraw + 64 * 128 * 4);
    const int t = threadIdx.x;
    const int s = *shift_p;
    const long R0 = (long)blockIdx.x * 64;

    #pragma unroll
    for (int it = 0; it < 8; it++) {
        int e = t + it * 256;
        ((float4*)xs)[e] = ((const float4*)g_AO)[R0 * 32 + e];
    }
    load_wsp(wsp, Wp, t);
    __syncthreads();

    const int c0 = t & 31;
    const int r0 = (t >> 5) * 8;
    ull accp[8][4];
    gemm_core(xs, wsp, c0, r0, accp);

    #pragma unroll
    for (int r = 0; r < 8; r++) {
        long R = R0 + r0 + r;
        int b  = (int)(R >> 14);
        int r1 = (int)(R >> 7) & 127;
        int r2 = (int)R & 127;
        int oh = (r1 + s) & 127;
        int ow = (r2 + s) & 127;
        float* drow = out + (((long)b * 128 + oh) * 128 + ow) * 128;
        #pragma unroll
        for (int m = 0; m < 4; m++) {
            int c = c0 + m * 32;
            float2 f = unpk2(accp[r][m]);
            drow[c] = f.x + f.y + bp[c];
        }
    }
}

// ---------------------------------------------------------------------------
extern "C" void kernel_launch(void* const* d_in, const int* in_sizes, int n_in,
                              void* d_out, int out_size)
{
    const float* x  = (const float*)d_in[0];
    const float* Wq = (const float*)d_in[1];
    const float* bq = (const float*)d_in[2];
    const float* Wk = (const float*)d_in[3];
    const float* bk = (const float*)d_in[4];
    const float* Wv = (const float*)d_in[5];
    const float* bv = (const float*)d_in[6];
    const float* Wp = (const float*)d_in[7];
    const float* bp = (const float*)d_in[8];
    const float* bt = (const float*)d_in[9];
    const int* shift = (const int*)d_in[10];
    float* out = (float*)d_out;

    const size_t smem = GEMM_SMEM_BYTES;   // 100864 B
    cudaFuncSetAttribute(proj_qkv_kernel, cudaFuncAttributeMaxDynamicSharedMemorySize, (int)smem);
    cudaFuncSetAttribute(out_proj_kernel, cudaFuncAttributeMaxDynamicSharedMemorySize, (int)smem);

    proj_qkv_kernel<<<512, 256, smem>>>(x, Wq, bq, Wk, bk, Wv, bv, shift);
    attn_kernel    <<<dim3(128, 4), 256>>>(bt);
    out_proj_kernel<<<512, 256, smem>>>(Wp, bp, shift, out);
}

// round 9
// speedup vs baseline: 2.4563x; 1.9161x over previous
#include <cuda_runtime.h>
#include <cuda_bf16.h>
#include <cstdint>

#define NH 4
#define DIMC 128
#define BT_N 2209   // 47^2

typedef unsigned long long ull;

// Per-pixel layouts (rolled space): 32768 rows x 128.
__device__ __align__(16) float g_Q [32768 * DIMC];
__device__ __align__(16) float g_K [32768 * DIMC];
__device__ __align__(16) float g_V [32768 * DIMC];
__device__ __align__(16) float g_AO[32768 * DIMC];

// ---- packed f32x2 helpers (projection GEMMs) ----
__device__ __forceinline__ ull pack2(float lo, float hi) {
    ull r; asm("mov.b64 %0,{%1,%2};" : "=l"(r) : "f"(lo), "f"(hi)); return r;
}
__device__ __forceinline__ ull fma2(ull a, ull b, ull c) {
    ull d; asm("fma.rn.f32x2 %0,%1,%2,%3;" : "=l"(d) : "l"(a), "l"(b), "l"(c)); return d;
}
__device__ __forceinline__ float2 unpk2(ull v) {
    float2 f; asm("mov.b64 {%0,%1},%2;" : "=f"(f.x), "=f"(f.y) : "l"(v)); return f;
}
__device__ __forceinline__ float ex2f(float x) {
    float r; asm("ex2.approx.f32 %0,%1;" : "=f"(r) : "f"(x)); return r;
}
__device__ __forceinline__ int reflect_idx(int p, int n) {
    if (p < 0) p = -p;
    else if (p >= n) p = 2 * n - 2 - p;
    return p;
}
__device__ __forceinline__ uint32_t bfpack_hi(float a, float b, float& ra, float& rb) {
    __nv_bfloat16 ha = __float2bfloat16(a), hb = __float2bfloat16(b);
    ra = __bfloat162float(ha); rb = __bfloat162float(hb);
    return (uint32_t)__bfloat16_as_ushort(ha) | ((uint32_t)__bfloat16_as_ushort(hb) << 16);
}
__device__ __forceinline__ uint32_t bfpack(float a, float b) {
    return (uint32_t)__bfloat16_as_ushort(__float2bfloat16(a)) |
           ((uint32_t)__bfloat16_as_ushort(__float2bfloat16(b)) << 16);
}

// mma.sync m16n8k16 bf16: D(f32x4) += A(4xb32) * B(2xb32)   (sm_80+, non-'a')
__device__ __forceinline__ void mma_bf16(float d[4], const uint32_t a[4], const uint32_t b[2]) {
    asm volatile(
        "mma.sync.aligned.m16n8k16.row.col.f32.bf16.bf16.f32 "
        "{%0,%1,%2,%3},{%4,%5,%6,%7},{%8,%9},{%0,%1,%2,%3};"
        : "+f"(d[0]), "+f"(d[1]), "+f"(d[2]), "+f"(d[3])
        : "r"(a[0]), "r"(a[1]), "r"(a[2]), "r"(a[3]), "r"(b[0]), "r"(b[1]));
}

// ---------------------------------------------------------------------------
// Packed-GEMM projection pieces (unchanged — passing).
// ---------------------------------------------------------------------------
#define GEMM_SMEM_BYTES (64 * 128 * 4 + 64 * 133 * 8)   // 100864

__device__ __forceinline__ void load_wsp(ull* wsp, const float* __restrict__ W, int t) {
    #pragma unroll
    for (int it = 0; it < 32; it++) {
        int e  = t + it * 256;
        int c  = e >> 6;
        int kp = e & 63;
        float2 wv = ((const float2*)W)[c * 64 + kp];
        wsp[kp * 133 + c] = pack2(wv.x, wv.y);
    }
}

__device__ __forceinline__ void gemm_core(const float* xs, const ull* wsp,
                                          int c0, int r0, ull accp[8][4]) {
    #pragma unroll
    for (int r = 0; r < 8; r++)
        #pragma unroll
        for (int m = 0; m < 4; m++) accp[r][m] = 0ull;

    for (int kp = 0; kp < 64; kp += 2) {
        ulonglong2 xu[8];
        #pragma unroll
        for (int r = 0; r < 8; r++)
            xu[r] = *(const ulonglong2*)(xs + (r0 + r) * 128 + kp * 2);
        #pragma unroll
        for (int m = 0; m < 4; m++) {
            ull w0 = wsp[kp * 133 + c0 + m * 32];
            ull w1 = wsp[(kp + 1) * 133 + c0 + m * 32];
            #pragma unroll
            for (int r = 0; r < 8; r++) {
                accp[r][m] = fma2(xu[r].x, w0, accp[r][m]);
                accp[r][m] = fma2(xu[r].y, w1, accp[r][m]);
            }
        }
    }
}

__global__ __launch_bounds__(256) void proj_qkv_kernel(
    const float* __restrict__ x,
    const float* __restrict__ Wq, const float* __restrict__ bq,
    const float* __restrict__ Wk, const float* __restrict__ bk,
    const float* __restrict__ Wv, const float* __restrict__ bv,
    const int* __restrict__ shift_p)
{
    extern __shared__ char smraw[];
    float* xs = (float*)smraw;
    ull*  wsp = (ull*)(smraw + 64 * 128 * 4);
    const int t = threadIdx.x;
    const int s = *shift_p;
    const long R0 = (long)blockIdx.x * 64;

    #pragma unroll
    for (int it = 0; it < 8; it++) {
        int e  = t + it * 256;
        int r  = e >> 5;
        int c4 = e & 31;
        long R = R0 + r;
        int b  = (int)(R >> 14);
        int r1 = (int)(R >> 7) & 127;
        int r2 = (int)R & 127;
        int hh = (r1 + s) & 127;
        int ww = (r2 + s) & 127;
        ((float4*)xs)[e] =
            ((const float4*)x)[(((long)b * 128 + hh) * 128 + ww) * 32 + c4];
    }

    const int c0 = t & 31;
    const int r0 = (t >> 5) * 8;
    #pragma unroll 1
    for (int pass = 0; pass < 3; pass++) {
        const float* W  = pass == 0 ? Wq : (pass == 1 ? Wk : Wv);
        const float* bb = pass == 0 ? bq : (pass == 1 ? bk : bv);
        float* g        = pass == 0 ? g_Q : (pass == 1 ? g_K : g_V);
        __syncthreads();
        load_wsp(wsp, W, t);
        __syncthreads();

        ull accp[8][4];
        gemm_core(xs, wsp, c0, r0, accp);

        #pragma unroll
        for (int m = 0; m < 4; m++) {
            int c = c0 + m * 32;
            float bias = bb[c];
            #pragma unroll
            for (int r = 0; r < 8; r++) {
                float2 f = unpk2(accp[r][m]);
                g[(R0 + r0 + r) * 128 + c] = f.x + f.y + bias;
            }
        }
    }
}

// ---------------------------------------------------------------------------
// attention: FA2-style mma.sync bf16 (split hi/lo for exactness).
// CTA = (window, head), 256 threads = 8 warps; warp owns 32 query rows.
// Bias row uses the reference's FLAT mapping: query r -> bias row 8+(r>>5),
// col (r&31) in the 47-stride table (NOT geometric window coords).
// ---------------------------------------------------------------------------
__device__ __forceinline__ int bidx(int rowbase, int k) {
    int ix = rowbase - (k >> 5) * 47 - (k & 31);
    return ix < 0 ? ix + BT_N : ix;
}

__global__ __launch_bounds__(256) void attn_kernel(const float* __restrict__ bias_table)
{
    __shared__ float bias_s[BT_N + 3];
    __shared__ uint32_t Khi_s[64 * 33], Klo_s[64 * 33];     // [key][dimpair], stride 33
    __shared__ uint32_t Vthi_s[32 * 33], Vtlo_s[32 * 33];   // [dim][keypair], stride 33
    __shared__ int rhs_s[32], rws_s[32];

    const int t    = threadIdx.x;
    const int wid  = t >> 5;
    const int lane = t & 31;
    const int g    = lane >> 2;     // groupID
    const int tg   = lane & 3;      // thread-in-group
    const int w = blockIdx.x;
    const int h = blockIdx.y;
    const int b  = w >> 6, wi = (w >> 3) & 7, wj = w & 7;
    const float LOG2E = 1.4426950408889634f;

    if (t < 32)       rhs_s[t]      = reflect_idx(wi * 16 + t - 8, 128);
    else if (t < 64)  rws_s[t - 32] = reflect_idx(wj * 16 + (t - 32) - 8, 128);
    for (int i = t; i < BT_N; i += 256) bias_s[i] = bias_table[i * NH + h] * LOG2E;

    // ---- Q fragments (held all kernel): [mb][kc][4] hi/lo ----
    uint32_t QH[2][2][4], QL[2][2][4];
    {
        const float qs = 0.17677669529663687f * LOG2E;
        #pragma unroll
        for (int mb = 0; mb < 2; mb++) {
            int r0 = wid * 32 + mb * 16 + g;
            int ii0 = r0 >> 4,        jj0 = r0 & 15;
            int ii1 = (r0 + 8) >> 4,  jj1 = (r0 + 8) & 15;
            const float* q0 = g_Q + (((long)b * 128 + wi * 16 + ii0) * 128 + wj * 16 + jj0) * 128 + h * 32;
            const float* q1 = g_Q + (((long)b * 128 + wi * 16 + ii1) * 128 + wj * 16 + jj1) * 128 + h * 32;
            #pragma unroll
            for (int kc = 0; kc < 2; kc++) {
                int d0 = kc * 16 + tg * 2;
                float2 f;
                float ra, rb;
                f = *(const float2*)(q0 + d0);
                QH[mb][kc][0] = bfpack_hi(f.x * qs, f.y * qs, ra, rb);
                QL[mb][kc][0] = bfpack(f.x * qs - ra, f.y * qs - rb);
                f = *(const float2*)(q1 + d0);
                QH[mb][kc][1] = bfpack_hi(f.x * qs, f.y * qs, ra, rb);
                QL[mb][kc][1] = bfpack(f.x * qs - ra, f.y * qs - rb);
                f = *(const float2*)(q0 + d0 + 8);
                QH[mb][kc][2] = bfpack_hi(f.x * qs, f.y * qs, ra, rb);
                QL[mb][kc][2] = bfpack(f.x * qs - ra, f.y * qs - rb);
                f = *(const float2*)(q1 + d0 + 8);
                QH[mb][kc][3] = bfpack_hi(f.x * qs, f.y * qs, ra, rb);
                QL[mb][kc][3] = bfpack(f.x * qs - ra, f.y * qs - rb);
            }
        }
    }
    // Bias row base (reference flat mapping): query r = wid*32 + mb*16 + g
    //   row term: r>>5 = wid, col term: r&31 = mb*16+g
    //   qoff = ((r>>5)+31)*47 + (r&31) + 23
    int qbase[2];
    qbase[0] = (wid + 31) * 47 + 0 * 16 + g + 23;
    qbase[1] = (wid + 31) * 47 + 1 * 16 + g + 23;

    float Of[2][4][4];
    #pragma unroll
    for (int mb = 0; mb < 2; mb++)
        #pragma unroll
        for (int nd = 0; nd < 4; nd++)
            #pragma unroll
            for (int i = 0; i < 4; i++) Of[mb][nd][i] = 0.f;
    float ls[4] = {0.f, 0.f, 0.f, 0.f};   // [mb*2 + rowhalf]

    #pragma unroll 1
    for (int tile = 0; tile < 16; tile++) {
        __syncthreads();    // prior compute done before restaging
        // ---- stage K: 64 keys x 32 dims, hi/lo ----
        #pragma unroll
        for (int it = 0; it < 2; it++) {
            int e   = t + it * 256;
            int key = e >> 3, d4 = e & 7;
            int u = tile * 2 + (key >> 5), v = key & 31;
            long krow = ((long)b * 128 + rhs_s[u]) * 128 + rws_s[v];
            float4 kv = *(const float4*)(g_K + krow * 128 + h * 32 + d4 * 4);
            float rx, ry, rz, rw;
            uint32_t h01 = bfpack_hi(kv.x, kv.y, rx, ry);
            uint32_t h23 = bfpack_hi(kv.z, kv.w, rz, rw);
            Khi_s[key * 33 + d4 * 2]     = h01;
            Khi_s[key * 33 + d4 * 2 + 1] = h23;
            Klo_s[key * 33 + d4 * 2]     = bfpack(kv.x - rx, kv.y - ry);
            Klo_s[key * 33 + d4 * 2 + 1] = bfpack(kv.z - rz, kv.w - rw);
        }
        // ---- stage V^T: [dim][keypair] hi/lo ----
        {
            int kp = t >> 3, d4 = t & 7;
            int k0 = 2 * kp, k1 = 2 * kp + 1;
            int u0 = tile * 2 + (k0 >> 5), v0 = k0 & 31;
            int u1 = tile * 2 + (k1 >> 5), v1 = k1 & 31;
            long row0 = ((long)b * 128 + rhs_s[u0]) * 128 + rws_s[v0];
            long row1 = ((long)b * 128 + rhs_s[u1]) * 128 + rws_s[v1];
            float4 a4 = *(const float4*)(g_V + row0 * 128 + h * 32 + d4 * 4);
            float4 c4 = *(const float4*)(g_V + row1 * 128 + h * 32 + d4 * 4);
            const float* av = (const float*)&a4;
            const float* cv = (const float*)&c4;
            #pragma unroll
            for (int i = 0; i < 4; i++) {
                int d = d4 * 4 + i;
                float ra, rc;
                Vthi_s[d * 33 + kp] = bfpack_hi(av[i], cv[i], ra, rc);
                Vtlo_s[d * 33 + kp] = bfpack(av[i] - ra, cv[i] - rc);
            }
        }
        __syncthreads();

        #pragma unroll 1
        for (int nb = 0; nb < 4; nb++) {
            // K fragments for ntiles j0=2nb, j1=2nb+1 : [j][kc][2]
            uint32_t KHf[2][2][2], KLf[2][2][2];
            #pragma unroll
            for (int j2 = 0; j2 < 2; j2++) {
                int key = (2 * nb + j2) * 8 + g;
                #pragma unroll
                for (int kc = 0; kc < 2; kc++) {
                    KHf[j2][kc][0] = Khi_s[key * 33 + kc * 8 + tg];
                    KHf[j2][kc][1] = Khi_s[key * 33 + kc * 8 + 4 + tg];
                    KLf[j2][kc][0] = Klo_s[key * 33 + kc * 8 + tg];
                    KLf[j2][kc][1] = Klo_s[key * 33 + kc * 8 + 4 + tg];
                }
            }
            // V fragments: [nd][2] for key-chunk kb = nb*16
            uint32_t VHf[4][2], VLf[4][2];
            #pragma unroll
            for (int nd = 0; nd < 4; nd++) {
                int d = nd * 8 + g;
                VHf[nd][0] = Vthi_s[d * 33 + nb * 8 + tg];
                VHf[nd][1] = Vthi_s[d * 33 + nb * 8 + 4 + tg];
                VLf[nd][0] = Vtlo_s[d * 33 + nb * 8 + tg];
                VLf[nd][1] = Vtlo_s[d * 33 + nb * 8 + 4 + tg];
            }
            #pragma unroll
            for (int mb = 0; mb < 2; mb++) {
                float S0[4] = {0.f, 0.f, 0.f, 0.f};
                float S1[4] = {0.f, 0.f, 0.f, 0.f};
                #pragma unroll
                for (int kc = 0; kc < 2; kc++) {
                    mma_bf16(S0, QH[mb][kc], KHf[0][kc]);
                    mma_bf16(S0, QL[mb][kc], KHf[0][kc]);
                    mma_bf16(S0, QH[mb][kc], KLf[0][kc]);
                    mma_bf16(S1, QH[mb][kc], KHf[1][kc]);
                    mma_bf16(S1, QL[mb][kc], KHf[1][kc]);
                    mma_bf16(S1, QH[mb][kc], KLf[1][kc]);
                }
                // softmax (fixed max), bias via 47-stride table
                int kg0 = tile * 64 + nb * 16 + tg * 2;
                int kg8 = kg0 + 8;
                int rb0 = qbase[mb];
                int rb8 = rb0 + 8;
                float p0 = ex2f(S0[0] + bias_s[bidx(rb0, kg0)]);
                float p1 = ex2f(S0[1] + bias_s[bidx(rb0, kg0 + 1)]);
                float p2 = ex2f(S0[2] + bias_s[bidx(rb8, kg0)]);
                float p3 = ex2f(S0[3] + bias_s[bidx(rb8, kg0 + 1)]);
                float p4 = ex2f(S1[0] + bias_s[bidx(rb0, kg8)]);
                float p5 = ex2f(S1[1] + bias_s[bidx(rb0, kg8 + 1)]);
                float p6 = ex2f(S1[2] + bias_s[bidx(rb8, kg8)]);
                float p7 = ex2f(S1[3] + bias_s[bidx(rb8, kg8 + 1)]);
                ls[mb * 2 + 0] += (p0 + p1) + (p4 + p5);
                ls[mb * 2 + 1] += (p2 + p3) + (p6 + p7);
                // P fragments (C->A identity): a0=(p0,p1) a1=(p2,p3) a2=(p4,p5) a3=(p6,p7)
                uint32_t PH[4], PL[4];
                float ra, rb;
                PH[0] = bfpack_hi(p0, p1, ra, rb); PL[0] = bfpack(p0 - ra, p1 - rb);
                PH[1] = bfpack_hi(p2, p3, ra, rb); PL[1] = bfpack(p2 - ra, p3 - rb);
                PH[2] = bfpack_hi(p4, p5, ra, rb); PL[2] = bfpack(p4 - ra, p5 - rb);
                PH[3] = bfpack_hi(p6, p7, ra, rb); PL[3] = bfpack(p6 - ra, p7 - rb);
                #pragma unroll
                for (int nd = 0; nd < 4; nd++) {
                    mma_bf16(Of[mb][nd], PH, VHf[nd]);
                    mma_bf16(Of[mb][nd], PL, VHf[nd]);
                    mma_bf16(Of[mb][nd], PH, VLf[nd]);
                }
            }
        }
    }

    // ---- finalize: l reduce within quad, scale, store ----
    #pragma unroll
    for (int i = 0; i < 4; i++) {
        ls[i] += __shfl_xor_sync(0xffffffffu, ls[i], 1);
        ls[i] += __shfl_xor_sync(0xffffffffu, ls[i], 2);
        ls[i] = 1.f / ls[i];
    }
    #pragma unroll
    for (int mb = 0; mb < 2; mb++) {
        int r0 = wid * 32 + mb * 16 + g;
        int ii0 = r0 >> 4,        jj0 = r0 & 15;
        int ii1 = (r0 + 8) >> 4,  jj1 = (r0 + 8) & 15;
        float* o0 = g_AO + (((long)b * 128 + wi * 16 + ii0) * 128 + wj * 16 + jj0) * 128 + h * 32;
        float* o1 = g_AO + (((long)b * 128 + wi * 16 + ii1) * 128 + wj * 16 + jj1) * 128 + h * 32;
        float invlo = ls[mb * 2 + 0];
        float invhi = ls[mb * 2 + 1];
        #pragma unroll
        for (int nd = 0; nd < 4; nd++) {
            float2 v;
            v.x = Of[mb][nd][0] * invlo; v.y = Of[mb][nd][1] * invlo;
            *(float2*)(o0 + nd * 8 + tg * 2) = v;
            v.x = Of[mb][nd][2] * invhi; v.y = Of[mb][nd][3] * invhi;
            *(float2*)(o1 + nd * 8 + tg * 2) = v;
        }
    }
}

// ---------------------------------------------------------------------------
// out_proj
// ---------------------------------------------------------------------------
__global__ __launch_bounds__(256) void out_proj_kernel(
    const float* __restrict__ Wp, const float* __restrict__ bp,
    const int* __restrict__ shift_p, float* __restrict__ out)
{
    extern __shared__ char smraw[];
    float* xs = (float*)smraw;
    ull*  wsp = (ull*)(smraw + 64 * 128 * 4);
    const int t = threadIdx.x;
    const int s = *shift_p;
    const long R0 = (long)blockIdx.x * 64;

    #pragma unroll
    for (int it = 0; it < 8; it++) {
        int e = t + it * 256;
        ((float4*)xs)[e] = ((const float4*)g_AO)[R0 * 32 + e];
    }
    load_wsp(wsp, Wp, t);
    __syncthreads();

    const int c0 = t & 31;
    const int r0 = (t >> 5) * 8;
    ull accp[8][4];
    gemm_core(xs, wsp, c0, r0, accp);

    #pragma unroll
    for (int r = 0; r < 8; r++) {
        long R = R0 + r0 + r;
        int b  = (int)(R >> 14);
        int r1 = (int)(R >> 7) & 127;
        int r2 = (int)R & 127;
        int oh = (r1 + s) & 127;
        int ow = (r2 + s) & 127;
        float* drow = out + (((long)b * 128 + oh) * 128 + ow) * 128;
        #pragma unroll
        for (int m = 0; m < 4; m++) {
            int c = c0 + m * 32;
            float2 f = unpk2(accp[r][m]);
            drow[c] = f.x + f.y + bp[c];
        }
    }
}

// ---------------------------------------------------------------------------
extern "C" void kernel_launch(void* const* d_in, const int* in_sizes, int n_in,
                              void* d_out, int out_size)
{
    const float* x  = (const float*)d_in[0];
    const float* Wq = (const float*)d_in[1];
    const float* bq = (const float*)d_in[2];
    const float* Wk = (const float*)d_in[3];
    const float* bk = (const float*)d_in[4];
    const float* Wv = (const float*)d_in[5];
    const float* bv = (const float*)d_in[6];
    const float* Wp = (const float*)d_in[7];
    const float* bp = (const float*)d_in[8];
    const float* bt = (const float*)d_in[9];
    const int* shift = (const int*)d_in[10];
    float* out = (float*)d_out;

    const size_t smem = GEMM_SMEM_BYTES;
    cudaFuncSetAttribute(proj_qkv_kernel, cudaFuncAttributeMaxDynamicSharedMemorySize, (int)smem);
    cudaFuncSetAttribute(out_proj_kernel, cudaFuncAttributeMaxDynamicSharedMemorySize, (int)smem);

    proj_qkv_kernel<<<512, 256, smem>>>(x, Wq, bq, Wk, bk, Wv, bv, shift);
    attn_kernel    <<<dim3(128, 4), 256>>>(bt);
    out_proj_kernel<<<512, 256, smem>>>(Wp, bp, shift, out);
}

// round 11
// speedup vs baseline: 3.3095x; 1.3473x over previous
#include <cuda_runtime.h>
#include <cuda_bf16.h>
#include <cstdint>

#define NH 4
#define DIMC 128
#define BT_N 2209   // 47^2

// Per-pixel layouts (rolled space): 32768 rows x 128.
__device__ __align__(16) float g_Q [32768 * DIMC];
__device__ __align__(16) float g_K [32768 * DIMC];
__device__ __align__(16) float g_V [32768 * DIMC];
__device__ __align__(16) float g_AO[32768 * DIMC];

__device__ __forceinline__ float ex2f(float x) {
    float r; asm("ex2.approx.f32 %0,%1;" : "=f"(r) : "f"(x)); return r;
}
__device__ __forceinline__ int reflect_idx(int p, int n) {
    if (p < 0) p = -p;
    else if (p >= n) p = 2 * n - 2 - p;
    return p;
}
// Split (a,b) into packed bf16 hi (returned; a in low half) and packed lo remainder.
__device__ __forceinline__ uint32_t bfsplit(float a, float b, uint32_t& lo) {
    uint32_t hi;
    asm("cvt.rn.bf16x2.f32 %0,%1,%2;" : "=r"(hi) : "f"(b), "f"(a));
    float ra = __uint_as_float(hi << 16);
    float rb = __uint_as_float(hi & 0xffff0000u);
    asm("cvt.rn.bf16x2.f32 %0,%1,%2;" : "=r"(lo) : "f"(b - rb), "f"(a - ra));
    return hi;
}

// mma.sync m16n8k16 bf16: D(f32x4) += A(4xb32) * B(2xb32)   (sm_80+, non-'a')
__device__ __forceinline__ void mma_bf16(float d[4], const uint32_t a[4], const uint32_t b[2]) {
    asm volatile(
        "mma.sync.aligned.m16n8k16.row.col.f32.bf16.bf16.f32 "
        "{%0,%1,%2,%3},{%4,%5,%6,%7},{%8,%9},{%0,%1,%2,%3};"
        : "+f"(d[0]), "+f"(d[1]), "+f"(d[2]), "+f"(d[3])
        : "r"(a[0]), "r"(a[1]), "r"(a[2]), "r"(a[3]), "r"(b[0]), "r"(b[1]));
}

// ---------------------------------------------------------------------------
// Split-bf16 MMA projection GEMM: C[64x128] = X[64x128] . W^T + b
// CTA 256 thr = 8 warps (4 m-tiles x 2 n-halves). W hi/lo staged in stride-68
// smem (>=64 entries per row! 68%32==4 -> conflict-free frag reads);
// X fp32 in smem, A-frags split on the fly.
// Exactness: Xhi.Whi + Xlo.Whi + Xhi.Wlo (err ~2^-17).
// ---------------------------------------------------------------------------
#define XS_STRIDE 132
#define WS_STRIDE 68
#define PROJ_SMEM (64 * XS_STRIDE * 4 + 2 * 128 * WS_STRIDE * 4)   // 103424

struct ProjSmem {
    float* xs;
    uint32_t* whi;
    uint32_t* wlo;
};
__device__ __forceinline__ ProjSmem proj_smem(char* smraw) {
    ProjSmem p;
    p.xs  = (float*)smraw;
    p.whi = (uint32_t*)(smraw + 64 * XS_STRIDE * 4);
    p.wlo = p.whi + 128 * WS_STRIDE;
    return p;
}

__device__ __forceinline__ void stage_W(ProjSmem& sm, const float* __restrict__ W, int t) {
    #pragma unroll
    for (int it = 0; it < 32; it++) {
        int e  = t + it * 256;
        int c  = e >> 6;           // 0..127
        int kp = e & 63;           // 0..63  (needs WS_STRIDE >= 64)
        float2 wv = ((const float2*)W)[c * 64 + kp];
        uint32_t lo, hi = bfsplit(wv.x, wv.y, lo);
        sm.whi[c * WS_STRIDE + kp] = hi;
        sm.wlo[c * WS_STRIDE + kp] = lo;
    }
}

// per-warp GEMM: rows r0..r0+15 (x2 halves), cols warp_n*64 .. +63
__device__ __forceinline__ void proj_mma_core(ProjSmem& sm, int r0, int warp_n,
                                              int grp, int tg, float acc[8][4]) {
    #pragma unroll
    for (int nt = 0; nt < 8; nt++)
        #pragma unroll
        for (int i = 0; i < 4; i++) acc[nt][i] = 0.f;

    #pragma unroll 1
    for (int kc = 0; kc < 8; kc++) {
        const float* x0 = sm.xs + (r0 + grp) * XS_STRIDE + kc * 16 + tg * 2;
        const float* x1 = x0 + 8 * XS_STRIDE;
        float2 f0 = *(const float2*)x0;
        float2 f1 = *(const float2*)x1;
        float2 f2 = *(const float2*)(x0 + 8);
        float2 f3 = *(const float2*)(x1 + 8);
        uint32_t AH[4], AL[4];
        AH[0] = bfsplit(f0.x, f0.y, AL[0]);
        AH[1] = bfsplit(f1.x, f1.y, AL[1]);
        AH[2] = bfsplit(f2.x, f2.y, AL[2]);
        AH[3] = bfsplit(f3.x, f3.y, AL[3]);
        #pragma unroll
        for (int nt = 0; nt < 8; nt++) {
            int cb = (warp_n * 64 + nt * 8 + grp) * WS_STRIDE + kc * 8 + tg;
            uint32_t bh[2] = { sm.whi[cb], sm.whi[cb + 4] };
            uint32_t bl[2] = { sm.wlo[cb], sm.wlo[cb + 4] };
            mma_bf16(acc[nt], AH, bh);
            mma_bf16(acc[nt], AL, bh);
            mma_bf16(acc[nt], AH, bl);
        }
    }
}

__global__ __launch_bounds__(256) void proj_qkv_kernel(
    const float* __restrict__ x,
    const float* __restrict__ Wq, const float* __restrict__ bq,
    const float* __restrict__ Wk, const float* __restrict__ bk,
    const float* __restrict__ Wv, const float* __restrict__ bv,
    const int* __restrict__ shift_p)
{
    extern __shared__ char smraw[];
    ProjSmem sm = proj_smem(smraw);
    const int t = threadIdx.x;
    const int wid = t >> 5, lane = t & 31, grp = lane >> 2, tg = lane & 3;
    const int warp_m = wid & 3, warp_n = wid >> 2;
    const int s = *shift_p;
    const long R0 = (long)blockIdx.x * 64;

    // gather 64 pixel rows (rolled space) into xs
    #pragma unroll
    for (int it = 0; it < 8; it++) {
        int e = t + it * 256;
        int r = e >> 5, c4 = e & 31;
        long R = R0 + r;
        int b  = (int)(R >> 14);
        int r1 = (int)(R >> 7) & 127;
        int r2 = (int)R & 127;
        int hh = (r1 + s) & 127;
        int ww = (r2 + s) & 127;
        ((float4*)(sm.xs + r * XS_STRIDE))[c4] =
            ((const float4*)x)[(((long)b * 128 + hh) * 128 + ww) * 32 + c4];
    }

    const int r0 = warp_m * 16;
    #pragma unroll 1
    for (int pass = 0; pass < 3; pass++) {
        const float* W  = pass == 0 ? Wq : (pass == 1 ? Wk : Wv);
        const float* bb = pass == 0 ? bq : (pass == 1 ? bk : bv);
        float* gOut     = pass == 0 ? g_Q : (pass == 1 ? g_K : g_V);
        __syncthreads();          // xs ready / prior W reads done
        stage_W(sm, W, t);
        __syncthreads();

        float acc[8][4];
        proj_mma_core(sm, r0, warp_n, grp, tg, acc);

        float* out0 = gOut + (R0 + r0 + grp) * 128;
        float* out1 = out0 + 8 * 128;
        #pragma unroll
        for (int nt = 0; nt < 8; nt++) {
            int c = warp_n * 64 + nt * 8 + tg * 2;
            float2 bias2 = *(const float2*)(bb + c);
            float2 v0 = { acc[nt][0] + bias2.x, acc[nt][1] + bias2.y };
            float2 v1 = { acc[nt][2] + bias2.x, acc[nt][3] + bias2.y };
            *(float2*)(out0 + c) = v0;
            *(float2*)(out1 + c) = v1;
        }
    }
}

__global__ __launch_bounds__(256) void out_proj_kernel(
    const float* __restrict__ Wp, const float* __restrict__ bp,
    const int* __restrict__ shift_p, float* __restrict__ out)
{
    extern __shared__ char smraw[];
    ProjSmem sm = proj_smem(smraw);
    const int t = threadIdx.x;
    const int wid = t >> 5, lane = t & 31, grp = lane >> 2, tg = lane & 3;
    const int warp_m = wid & 3, warp_n = wid >> 2;
    const int s = *shift_p;
    const long R0 = (long)blockIdx.x * 64;

    #pragma unroll
    for (int it = 0; it < 8; it++) {
        int e = t + it * 256;
        int r = e >> 5, c4 = e & 31;
        ((float4*)(sm.xs + r * XS_STRIDE))[c4] = ((const float4*)g_AO)[R0 * 32 + e];
    }
    stage_W(sm, Wp, t);
    __syncthreads();

    const int r0 = warp_m * 16;
    float acc[8][4];
    proj_mma_core(sm, r0, warp_n, grp, tg, acc);

    // scatter with roll
    long R_0 = R0 + r0 + grp;
    long R_1 = R_0 + 8;
    int b0 = (int)(R_0 >> 14), r10 = (int)(R_0 >> 7) & 127, r20 = (int)R_0 & 127;
    int b1 = (int)(R_1 >> 14), r11 = (int)(R_1 >> 7) & 127, r21 = (int)R_1 & 127;
    float* drow0 = out + (((long)b0 * 128 + ((r10 + s) & 127)) * 128 + ((r20 + s) & 127)) * 128;
    float* drow1 = out + (((long)b1 * 128 + ((r11 + s) & 127)) * 128 + ((r21 + s) & 127)) * 128;
    #pragma unroll
    for (int nt = 0; nt < 8; nt++) {
        int c = warp_n * 64 + nt * 8 + tg * 2;
        float2 bias2 = *(const float2*)(bp + c);
        float2 v0 = { acc[nt][0] + bias2.x, acc[nt][1] + bias2.y };
        float2 v1 = { acc[nt][2] + bias2.x, acc[nt][3] + bias2.y };
        *(float2*)(drow0 + c) = v0;
        *(float2*)(drow1 + c) = v1;
    }
}

// ---------------------------------------------------------------------------
// attention: FA2-style mma.sync bf16 (split hi/lo), stride-36 smem
// (conflict-free fragment reads), single-cvt bf16x2 splits.
// Bias row uses the reference's FLAT mapping: query r -> row 8+(r>>5), col r&31.
// ---------------------------------------------------------------------------
#define KST 36
__device__ __forceinline__ int bidx(int rowbase, int k) {
    int ix = rowbase - (k >> 5) * 47 - (k & 31);
    return ix < 0 ? ix + BT_N : ix;
}

__global__ __launch_bounds__(256) void attn_kernel(const float* __restrict__ bias_table)
{
    __shared__ float bias_s[BT_N + 3];
    __shared__ uint32_t Khi_s[64 * KST], Klo_s[64 * KST];     // [key][dimpair<=15]
    __shared__ uint32_t Vthi_s[32 * KST], Vtlo_s[32 * KST];   // [dim][keypair<=31]
    __shared__ int rhs_s[32], rws_s[32];

    const int t    = threadIdx.x;
    const int wid  = t >> 5;
    const int lane = t & 31;
    const int g    = lane >> 2;
    const int tg   = lane & 3;
    const int w = blockIdx.x;
    const int h = blockIdx.y;
    const int b  = w >> 6, wi = (w >> 3) & 7, wj = w & 7;
    const float LOG2E = 1.4426950408889634f;

    if (t < 32)       rhs_s[t]      = reflect_idx(wi * 16 + t - 8, 128);
    else if (t < 64)  rws_s[t - 32] = reflect_idx(wj * 16 + (t - 32) - 8, 128);
    for (int i = t; i < BT_N; i += 256) bias_s[i] = bias_table[i * NH + h] * LOG2E;

    // ---- Q fragments (held all kernel): [mb][kc][4] hi/lo ----
    uint32_t QH[2][2][4], QL[2][2][4];
    {
        const float qs = 0.17677669529663687f * LOG2E;
        #pragma unroll
        for (int mb = 0; mb < 2; mb++) {
            int r0 = wid * 32 + mb * 16 + g;
            int ii0 = r0 >> 4,        jj0 = r0 & 15;
            int ii1 = (r0 + 8) >> 4,  jj1 = (r0 + 8) & 15;
            const float* q0 = g_Q + (((long)b * 128 + wi * 16 + ii0) * 128 + wj * 16 + jj0) * 128 + h * 32;
            const float* q1 = g_Q + (((long)b * 128 + wi * 16 + ii1) * 128 + wj * 16 + jj1) * 128 + h * 32;
            #pragma unroll
            for (int kc = 0; kc < 2; kc++) {
                int d0 = kc * 16 + tg * 2;
                float2 f;
                f = *(const float2*)(q0 + d0);
                QH[mb][kc][0] = bfsplit(f.x * qs, f.y * qs, QL[mb][kc][0]);
                f = *(const float2*)(q1 + d0);
                QH[mb][kc][1] = bfsplit(f.x * qs, f.y * qs, QL[mb][kc][1]);
                f = *(const float2*)(q0 + d0 + 8);
                QH[mb][kc][2] = bfsplit(f.x * qs, f.y * qs, QL[mb][kc][2]);
                f = *(const float2*)(q1 + d0 + 8);
                QH[mb][kc][3] = bfsplit(f.x * qs, f.y * qs, QL[mb][kc][3]);
            }
        }
    }
    // flat bias mapping: qoff = ((r>>5)+31)*47 + (r&31) + 23, r = wid*32+mb*16+g
    int qbase[2];
    qbase[0] = (wid + 31) * 47 + 0 * 16 + g + 23;
    qbase[1] = (wid + 31) * 47 + 1 * 16 + g + 23;

    float Of[2][4][4];
    #pragma unroll
    for (int mb = 0; mb < 2; mb++)
        #pragma unroll
        for (int nd = 0; nd < 4; nd++)
            #pragma unroll
            for (int i = 0; i < 4; i++) Of[mb][nd][i] = 0.f;
    float ls[4] = {0.f, 0.f, 0.f, 0.f};

    #pragma unroll 1
    for (int tile = 0; tile < 16; tile++) {
        __syncthreads();
        // ---- stage K: 64 keys x 32 dims, hi/lo ----
        #pragma unroll
        for (int it = 0; it < 2; it++) {
            int e   = t + it * 256;
            int key = e >> 3, d4 = e & 7;
            int u = tile * 2 + (key >> 5), v = key & 31;
            long krow = ((long)b * 128 + rhs_s[u]) * 128 + rws_s[v];
            float4 kv = *(const float4*)(g_K + krow * 128 + h * 32 + d4 * 4);
            uint32_t l01, l23;
            uint32_t h01 = bfsplit(kv.x, kv.y, l01);
            uint32_t h23 = bfsplit(kv.z, kv.w, l23);
            Khi_s[key * KST + d4 * 2]     = h01;
            Khi_s[key * KST + d4 * 2 + 1] = h23;
            Klo_s[key * KST + d4 * 2]     = l01;
            Klo_s[key * KST + d4 * 2 + 1] = l23;
        }
        // ---- stage V^T: [dim][keypair] hi/lo ----
        {
            int kp = t >> 3, d4 = t & 7;
            int k0 = 2 * kp, k1 = 2 * kp + 1;
            int u0 = tile * 2 + (k0 >> 5), v0 = k0 & 31;
            int u1 = tile * 2 + (k1 >> 5), v1 = k1 & 31;
            long row0 = ((long)b * 128 + rhs_s[u0]) * 128 + rws_s[v0];
            long row1 = ((long)b * 128 + rhs_s[u1]) * 128 + rws_s[v1];
            float4 a4 = *(const float4*)(g_V + row0 * 128 + h * 32 + d4 * 4);
            float4 c4 = *(const float4*)(g_V + row1 * 128 + h * 32 + d4 * 4);
            const float* av = (const float*)&a4;
            const float* cv = (const float*)&c4;
            #pragma unroll
            for (int i = 0; i < 4; i++) {
                int d = d4 * 4 + i;
                uint32_t lo;
                Vthi_s[d * KST + kp] = bfsplit(av[i], cv[i], lo);
                Vtlo_s[d * KST + kp] = lo;
            }
        }
        __syncthreads();

        #pragma unroll 1
        for (int nb = 0; nb < 4; nb++) {
            uint32_t KHf[2][2][2], KLf[2][2][2];
            #pragma unroll
            for (int j2 = 0; j2 < 2; j2++) {
                int key = (2 * nb + j2) * 8 + g;
                #pragma unroll
                for (int kc = 0; kc < 2; kc++) {
                    KHf[j2][kc][0] = Khi_s[key * KST + kc * 8 + tg];
                    KHf[j2][kc][1] = Khi_s[key * KST + kc * 8 + 4 + tg];
                    KLf[j2][kc][0] = Klo_s[key * KST + kc * 8 + tg];
                    KLf[j2][kc][1] = Klo_s[key * KST + kc * 8 + 4 + tg];
                }
            }
            uint32_t VHf[4][2], VLf[4][2];
            #pragma unroll
            for (int nd = 0; nd < 4; nd++) {
                int d = nd * 8 + g;
                VHf[nd][0] = Vthi_s[d * KST + nb * 8 + tg];
                VHf[nd][1] = Vthi_s[d * KST + nb * 8 + 4 + tg];
                VLf[nd][0] = Vtlo_s[d * KST + nb * 8 + tg];
                VLf[nd][1] = Vtlo_s[d * KST + nb * 8 + 4 + tg];
            }
            #pragma unroll
            for (int mb = 0; mb < 2; mb++) {
                float S0[4] = {0.f, 0.f, 0.f, 0.f};
                float S1[4] = {0.f, 0.f, 0.f, 0.f};
                #pragma unroll
                for (int kc = 0; kc < 2; kc++) {
                    mma_bf16(S0, QH[mb][kc], KHf[0][kc]);
                    mma_bf16(S0, QL[mb][kc], KHf[0][kc]);
                    mma_bf16(S0, QH[mb][kc], KLf[0][kc]);
                    mma_bf16(S1, QH[mb][kc], KHf[1][kc]);
                    mma_bf16(S1, QL[mb][kc], KHf[1][kc]);
                    mma_bf16(S1, QH[mb][kc], KLf[1][kc]);
                }
                int kg0 = tile * 64 + nb * 16 + tg * 2;
                int kg8 = kg0 + 8;
                int rb0 = qbase[mb];
                int rb8 = rb0 + 8;
                float p0 = ex2f(S0[0] + bias_s[bidx(rb0, kg0)]);
                float p1 = ex2f(S0[1] + bias_s[bidx(rb0, kg0 + 1)]);
                float p2 = ex2f(S0[2] + bias_s[bidx(rb8, kg0)]);
                float p3 = ex2f(S0[3] + bias_s[bidx(rb8, kg0 + 1)]);
                float p4 = ex2f(S1[0] + bias_s[bidx(rb0, kg8)]);
                float p5 = ex2f(S1[1] + bias_s[bidx(rb0, kg8 + 1)]);
                float p6 = ex2f(S1[2] + bias_s[bidx(rb8, kg8)]);
                float p7 = ex2f(S1[3] + bias_s[bidx(rb8, kg8 + 1)]);
                ls[mb * 2 + 0] += (p0 + p1) + (p4 + p5);
                ls[mb * 2 + 1] += (p2 + p3) + (p6 + p7);
                uint32_t PH[4], PL[4];
                PH[0] = bfsplit(p0, p1, PL[0]);
                PH[1] = bfsplit(p2, p3, PL[1]);
                PH[2] = bfsplit(p4, p5, PL[2]);
                PH[3] = bfsplit(p6, p7, PL[3]);
                #pragma unroll
                for (int nd = 0; nd < 4; nd++) {
                    mma_bf16(Of[mb][nd], PH, VHf[nd]);
                    mma_bf16(Of[mb][nd], PL, VHf[nd]);
                    mma_bf16(Of[mb][nd], PH, VLf[nd]);
                }
            }
        }
    }

    // ---- finalize ----
    #pragma unroll
    for (int i = 0; i < 4; i++) {
        ls[i] += __shfl_xor_sync(0xffffffffu, ls[i], 1);
        ls[i] += __shfl_xor_sync(0xffffffffu, ls[i], 2);
        ls[i] = 1.f / ls[i];
    }
    #pragma unroll
    for (int mb = 0; mb < 2; mb++) {
        int r0 = wid * 32 + mb * 16 + g;
        int ii0 = r0 >> 4,        jj0 = r0 & 15;
        int ii1 = (r0 + 8) >> 4,  jj1 = (r0 + 8) & 15;
        float* o0 = g_AO + (((long)b * 128 + wi * 16 + ii0) * 128 + wj * 16 + jj0) * 128 + h * 32;
        float* o1 = g_AO + (((long)b * 128 + wi * 16 + ii1) * 128 + wj * 16 + jj1) * 128 + h * 32;
        float invlo = ls[mb * 2 + 0];
        float invhi = ls[mb * 2 + 1];
        #pragma unroll
        for (int nd = 0; nd < 4; nd++) {
            float2 v;
            v.x = Of[mb][nd][0] * invlo; v.y = Of[mb][nd][1] * invlo;
            *(float2*)(o0 + nd * 8 + tg * 2) = v;
            v.x = Of[mb][nd][2] * invhi; v.y = Of[mb][nd][3] * invhi;
            *(float2*)(o1 + nd * 8 + tg * 2) = v;
        }
    }
}

// ---------------------------------------------------------------------------
extern "C" void kernel_launch(void* const* d_in, const int* in_sizes, int n_in,
                              void* d_out, int out_size)
{
    const float* x  = (const float*)d_in[0];
    const float* Wq = (const float*)d_in[1];
    const float* bq = (const float*)d_in[2];
    const float* Wk = (const float*)d_in[3];
    const float* bk = (const float*)d_in[4];
    const float* Wv = (const float*)d_in[5];
    const float* bv = (const float*)d_in[6];
    const float* Wp = (const float*)d_in[7];
    const float* bp = (const float*)d_in[8];
    const float* bt = (const float*)d_in[9];
    const int* shift = (const int*)d_in[10];
    float* out = (float*)d_out;

    cudaFuncSetAttribute(proj_qkv_kernel, cudaFuncAttributeMaxDynamicSharedMemorySize, PROJ_SMEM);
    cudaFuncSetAttribute(out_proj_kernel, cudaFuncAttributeMaxDynamicSharedMemorySize, PROJ_SMEM);

    proj_qkv_kernel<<<512, 256, PROJ_SMEM>>>(x, Wq, bq, Wk, bk, Wv, bv, shift);
    attn_kernel    <<<dim3(128, 4), 256>>>(bt);
    out_proj_kernel<<<512, 256, PROJ_SMEM>>>(Wp, bp, shift, out);
}

// round 12
// speedup vs baseline: 3.4258x; 1.0351x over previous
#include <cuda_runtime.h>
#include <cuda_bf16.h>
#include <cstdint>

#define NH 4
#define DIMC 128
#define BT_N 2209   // 47^2

// Per-pixel layouts (rolled space): 32768 rows x 128.
__device__ __align__(16) float g_Q [32768 * DIMC];
__device__ __align__(16) float g_K [32768 * DIMC];
__device__ __align__(16) float g_V [32768 * DIMC];
__device__ __align__(16) float g_AO[32768 * DIMC];

__device__ __forceinline__ float ex2f(float x) {
    float r; asm("ex2.approx.f32 %0,%1;" : "=f"(r) : "f"(x)); return r;
}
__device__ __forceinline__ int reflect_idx(int p, int n) {
    if (p < 0) p = -p;
    else if (p >= n) p = 2 * n - 2 - p;
    return p;
}
// Split (a,b) into packed bf16 hi (returned; a in low half) and packed lo remainder.
__device__ __forceinline__ uint32_t bfsplit(float a, float b, uint32_t& lo) {
    uint32_t hi;
    asm("cvt.rn.bf16x2.f32 %0,%1,%2;" : "=r"(hi) : "f"(b), "f"(a));
    float ra = __uint_as_float(hi << 16);
    float rb = __uint_as_float(hi & 0xffff0000u);
    asm("cvt.rn.bf16x2.f32 %0,%1,%2;" : "=r"(lo) : "f"(b - rb), "f"(a - ra));
    return hi;
}

// mma.sync m16n8k16 bf16: D(f32x4) += A(4xb32) * B(2xb32)   (sm_80+, non-'a')
__device__ __forceinline__ void mma_bf16(float d[4], const uint32_t a[4], const uint32_t b[2]) {
    asm volatile(
        "mma.sync.aligned.m16n8k16.row.col.f32.bf16.bf16.f32 "
        "{%0,%1,%2,%3},{%4,%5,%6,%7},{%8,%9},{%0,%1,%2,%3};"
        : "+f"(d[0]), "+f"(d[1]), "+f"(d[2]), "+f"(d[3])
        : "r"(a[0]), "r"(a[1]), "r"(a[2]), "r"(a[3]), "r"(b[0]), "r"(b[1]));
}

// ---------------------------------------------------------------------------
// Split-bf16 MMA projection GEMM (passing, unchanged from round 11).
// ---------------------------------------------------------------------------
#define XS_STRIDE 132
#define WS_STRIDE 68
#define PROJ_SMEM (64 * XS_STRIDE * 4 + 2 * 128 * WS_STRIDE * 4)   // 103424

struct ProjSmem {
    float* xs;
    uint32_t* whi;
    uint32_t* wlo;
};
__device__ __forceinline__ ProjSmem proj_smem(char* smraw) {
    ProjSmem p;
    p.xs  = (float*)smraw;
    p.whi = (uint32_t*)(smraw + 64 * XS_STRIDE * 4);
    p.wlo = p.whi + 128 * WS_STRIDE;
    return p;
}

__device__ __forceinline__ void stage_W(ProjSmem& sm, const float* __restrict__ W, int t) {
    #pragma unroll
    for (int it = 0; it < 32; it++) {
        int e  = t + it * 256;
        int c  = e >> 6;
        int kp = e & 63;
        float2 wv = ((const float2*)W)[c * 64 + kp];
        uint32_t lo, hi = bfsplit(wv.x, wv.y, lo);
        sm.whi[c * WS_STRIDE + kp] = hi;
        sm.wlo[c * WS_STRIDE + kp] = lo;
    }
}

__device__ __forceinline__ void proj_mma_core(ProjSmem& sm, int r0, int warp_n,
                                              int grp, int tg, float acc[8][4]) {
    #pragma unroll
    for (int nt = 0; nt < 8; nt++)
        #pragma unroll
        for (int i = 0; i < 4; i++) acc[nt][i] = 0.f;

    #pragma unroll 1
    for (int kc = 0; kc < 8; kc++) {
        const float* x0 = sm.xs + (r0 + grp) * XS_STRIDE + kc * 16 + tg * 2;
        const float* x1 = x0 + 8 * XS_STRIDE;
        float2 f0 = *(const float2*)x0;
        float2 f1 = *(const float2*)x1;
        float2 f2 = *(const float2*)(x0 + 8);
        float2 f3 = *(const float2*)(x1 + 8);
        uint32_t AH[4], AL[4];
        AH[0] = bfsplit(f0.x, f0.y, AL[0]);
        AH[1] = bfsplit(f1.x, f1.y, AL[1]);
        AH[2] = bfsplit(f2.x, f2.y, AL[2]);
        AH[3] = bfsplit(f3.x, f3.y, AL[3]);
        #pragma unroll
        for (int nt = 0; nt < 8; nt++) {
            int cb = (warp_n * 64 + nt * 8 + grp) * WS_STRIDE + kc * 8 + tg;
            uint32_t bh[2] = { sm.whi[cb], sm.whi[cb + 4] };
            uint32_t bl[2] = { sm.wlo[cb], sm.wlo[cb + 4] };
            mma_bf16(acc[nt], AH, bh);
            mma_bf16(acc[nt], AL, bh);
            mma_bf16(acc[nt], AH, bl);
        }
    }
}

__global__ __launch_bounds__(256) void proj_qkv_kernel(
    const float* __restrict__ x,
    const float* __restrict__ Wq, const float* __restrict__ bq,
    const float* __restrict__ Wk, const float* __restrict__ bk,
    const float* __restrict__ Wv, const float* __restrict__ bv,
    const int* __restrict__ shift_p)
{
    extern __shared__ char smraw[];
    ProjSmem sm = proj_smem(smraw);
    const int t = threadIdx.x;
    const int wid = t >> 5, lane = t & 31, grp = lane >> 2, tg = lane & 3;
    const int warp_m = wid & 3, warp_n = wid >> 2;
    const int s = *shift_p;
    const long R0 = (long)blockIdx.x * 64;

    #pragma unroll
    for (int it = 0; it < 8; it++) {
        int e = t + it * 256;
        int r = e >> 5, c4 = e & 31;
        long R = R0 + r;
        int b  = (int)(R >> 14);
        int r1 = (int)(R >> 7) & 127;
        int r2 = (int)R & 127;
        int hh = (r1 + s) & 127;
        int ww = (r2 + s) & 127;
        ((float4*)(sm.xs + r * XS_STRIDE))[c4] =
            ((const float4*)x)[(((long)b * 128 + hh) * 128 + ww) * 32 + c4];
    }

    const int r0 = warp_m * 16;
    #pragma unroll 1
    for (int pass = 0; pass < 3; pass++) {
        const float* W  = pass == 0 ? Wq : (pass == 1 ? Wk : Wv);
        const float* bb = pass == 0 ? bq : (pass == 1 ? bk : bv);
        float* gOut     = pass == 0 ? g_Q : (pass == 1 ? g_K : g_V);
        __syncthreads();
        stage_W(sm, W, t);
        __syncthreads();

        float acc[8][4];
        proj_mma_core(sm, r0, warp_n, grp, tg, acc);

        float* out0 = gOut + (R0 + r0 + grp) * 128;
        float* out1 = out0 + 8 * 128;
        #pragma unroll
        for (int nt = 0; nt < 8; nt++) {
            int c = warp_n * 64 + nt * 8 + tg * 2;
            float2 bias2 = *(const float2*)(bb + c);
            float2 v0 = { acc[nt][0] + bias2.x, acc[nt][1] + bias2.y };
            float2 v1 = { acc[nt][2] + bias2.x, acc[nt][3] + bias2.y };
            *(float2*)(out0 + c) = v0;
            *(float2*)(out1 + c) = v1;
        }
    }
}

__global__ __launch_bounds__(256) void out_proj_kernel(
    const float* __restrict__ Wp, const float* __restrict__ bp,
    const int* __restrict__ shift_p, float* __restrict__ out)
{
    extern __shared__ char smraw[];
    ProjSmem sm = proj_smem(smraw);
    const int t = threadIdx.x;
    const int wid = t >> 5, lane = t & 31, grp = lane >> 2, tg = lane & 3;
    const int warp_m = wid & 3, warp_n = wid >> 2;
    const int s = *shift_p;
    const long R0 = (long)blockIdx.x * 64;

    #pragma unroll
    for (int it = 0; it < 8; it++) {
        int e = t + it * 256;
        int r = e >> 5, c4 = e & 31;
        ((float4*)(sm.xs + r * XS_STRIDE))[c4] = ((const float4*)g_AO)[R0 * 32 + e];
    }
    stage_W(sm, Wp, t);
    __syncthreads();

    const int r0 = warp_m * 16;
    float acc[8][4];
    proj_mma_core(sm, r0, warp_n, grp, tg, acc);

    long R_0 = R0 + r0 + grp;
    long R_1 = R_0 + 8;
    int b0 = (int)(R_0 >> 14), r10 = (int)(R_0 >> 7) & 127, r20 = (int)R_0 & 127;
    int b1 = (int)(R_1 >> 14), r11 = (int)(R_1 >> 7) & 127, r21 = (int)R_1 & 127;
    float* drow0 = out + (((long)b0 * 128 + ((r10 + s) & 127)) * 128 + ((r20 + s) & 127)) * 128;
    float* drow1 = out + (((long)b1 * 128 + ((r11 + s) & 127)) * 128 + ((r21 + s) & 127)) * 128;
    #pragma unroll
    for (int nt = 0; nt < 8; nt++) {
        int c = warp_n * 64 + nt * 8 + tg * 2;
        float2 bias2 = *(const float2*)(bp + c);
        float2 v0 = { acc[nt][0] + bias2.x, acc[nt][1] + bias2.y };
        float2 v1 = { acc[nt][2] + bias2.x, acc[nt][3] + bias2.y };
        *(float2*)(drow0 + c) = v0;
        *(float2*)(drow1 + c) = v1;
    }
}

// ---------------------------------------------------------------------------
// attention: FA2-style mma.sync bf16 (split hi/lo), double-buffered K/V tiles
// (1 sync per tile, register prefetch of next tile overlaps LDG with MMA).
// Dynamic smem 64.4 KB, 2 CTAs/SM pinned.
// Bias row uses the reference's FLAT mapping: query r -> row 8+(r>>5), col r&31.
// ---------------------------------------------------------------------------
#define KST 36
#define ATTN_SMEM 64416
__device__ __forceinline__ int bidx(int rowbase, int k) {
    int ix = rowbase - (k >> 5) * 47 - (k & 31);
    return ix < 0 ? ix + BT_N : ix;
}

__global__ __launch_bounds__(256, 2) void attn_kernel(const float* __restrict__ bias_table)
{
    extern __shared__ __align__(16) char smb[];
    float*    bias_s = (float*)smb;                        // 2212 floats (pad) -> 8864 B
    uint32_t* KhiB   = (uint32_t*)(smb + 8864);            // [buf][64*KST]
    uint32_t* KloB   = KhiB + 2 * 64 * KST;
    uint32_t* VthiB  = KloB + 2 * 64 * KST;                // [buf][32*KST]
    uint32_t* VtloB  = VthiB + 2 * 32 * KST;
    int*      rhs_s  = (int*)(VtloB + 2 * 32 * KST);
    int*      rws_s  = rhs_s + 32;

    const int t    = threadIdx.x;
    const int wid  = t >> 5;
    const int lane = t & 31;
    const int g    = lane >> 2;
    const int tg   = lane & 3;
    const int w = blockIdx.x;
    const int h = blockIdx.y;
    const int b  = w >> 6, wi = (w >> 3) & 7, wj = w & 7;
    const float LOG2E = 1.4426950408889634f;

    if (t < 32)       rhs_s[t]      = reflect_idx(wi * 16 + t - 8, 128);
    else if (t < 64)  rws_s[t - 32] = reflect_idx(wj * 16 + (t - 32) - 8, 128);
    for (int i = t; i < BT_N; i += 256) bias_s[i] = bias_table[i * NH + h] * LOG2E;

    // ---- Q fragments (held all kernel): [mb][kc][4] hi/lo ----
    uint32_t QH[2][2][4], QL[2][2][4];
    {
        const float qs = 0.17677669529663687f * LOG2E;
        #pragma unroll
        for (int mb = 0; mb < 2; mb++) {
            int r0 = wid * 32 + mb * 16 + g;
            int ii0 = r0 >> 4,        jj0 = r0 & 15;
            int ii1 = (r0 + 8) >> 4,  jj1 = (r0 + 8) & 15;
            const float* q0 = g_Q + (((long)b * 128 + wi * 16 + ii0) * 128 + wj * 16 + jj0) * 128 + h * 32;
            const float* q1 = g_Q + (((long)b * 128 + wi * 16 + ii1) * 128 + wj * 16 + jj1) * 128 + h * 32;
            #pragma unroll
            for (int kc = 0; kc < 2; kc++) {
                int d0 = kc * 16 + tg * 2;
                float2 f;
                f = *(const float2*)(q0 + d0);
                QH[mb][kc][0] = bfsplit(f.x * qs, f.y * qs, QL[mb][kc][0]);
                f = *(const float2*)(q1 + d0);
                QH[mb][kc][1] = bfsplit(f.x * qs, f.y * qs, QL[mb][kc][1]);
                f = *(const float2*)(q0 + d0 + 8);
                QH[mb][kc][2] = bfsplit(f.x * qs, f.y * qs, QL[mb][kc][2]);
                f = *(const float2*)(q1 + d0 + 8);
                QH[mb][kc][3] = bfsplit(f.x * qs, f.y * qs, QL[mb][kc][3]);
            }
        }
    }
    // flat bias mapping: qoff = ((r>>5)+31)*47 + (r&31) + 23, r = wid*32+mb*16+g
    int qbase[2];
    qbase[0] = (wid + 31) * 47 + 0 * 16 + g + 23;
    qbase[1] = (wid + 31) * 47 + 1 * 16 + g + 23;

    float Of[2][4][4];
    #pragma unroll
    for (int mb = 0; mb < 2; mb++)
        #pragma unroll
        for (int nd = 0; nd < 4; nd++)
            #pragma unroll
            for (int i = 0; i < 4; i++) Of[mb][nd][i] = 0.f;
    float ls[4] = {0.f, 0.f, 0.f, 0.f};

    // per-thread staging coordinates (fixed)
    const int kKey0 = t >> 3,        kD4 = t & 7;       // K: e=t
    const int kKey1 = (t + 256) >> 3;                   // K: e=t+256 (same d4)
    const int vKp   = t >> 3,        vD4 = t & 7;       // V: keypair, dim-quad

    __syncthreads();   // rhs/rws/bias visible

    // ---- stage tile 0 ----
    {
        #pragma unroll
        for (int it = 0; it < 2; it++) {
            int key = it == 0 ? kKey0 : kKey1;
            int u = (key >> 5), v = key & 31;
            long krow = ((long)b * 128 + rhs_s[u]) * 128 + rws_s[v];
            float4 kv = *(const float4*)(g_K + krow * 128 + h * 32 + kD4 * 4);
            uint32_t l01, l23;
            uint32_t h01 = bfsplit(kv.x, kv.y, l01);
            uint32_t h23 = bfsplit(kv.z, kv.w, l23);
            KhiB[key * KST + kD4 * 2]     = h01;
            KhiB[key * KST + kD4 * 2 + 1] = h23;
            KloB[key * KST + kD4 * 2]     = l01;
            KloB[key * KST + kD4 * 2 + 1] = l23;
        }
        int k0 = 2 * vKp, k1 = 2 * vKp + 1;
        long row0 = ((long)b * 128 + rhs_s[k0 >> 5]) * 128 + rws_s[k0 & 31];
        long row1 = ((long)b * 128 + rhs_s[k1 >> 5]) * 128 + rws_s[k1 & 31];
        float4 a4 = *(const float4*)(g_V + row0 * 128 + h * 32 + vD4 * 4);
        float4 c4 = *(const float4*)(g_V + row1 * 128 + h * 32 + vD4 * 4);
        const float* av = (const float*)&a4;
        const float* cv = (const float*)&c4;
        #pragma unroll
        for (int i = 0; i < 4; i++) {
            int d = vD4 * 4 + i;
            uint32_t lo;
            VthiB[d * KST + vKp] = bfsplit(av[i], cv[i], lo);
            VtloB[d * KST + vKp] = lo;
        }
    }
    __syncthreads();

    #pragma unroll 1
    for (int tile = 0; tile < 16; tile++) {
        const int buf  = tile & 1;
        const int nbuf = buf ^ 1;
        const bool pf  = (tile < 15);

        // ---- prefetch next tile into registers (LDG overlaps compute) ----
        float4 pkA, pkB, pvA, pvB;
        if (pf) {
            int nt2 = (tile + 1) * 2;
            {
                int u = nt2 + (kKey0 >> 5), v = kKey0 & 31;
                long krow = ((long)b * 128 + rhs_s[u]) * 128 + rws_s[v];
                pkA = *(const float4*)(g_K + krow * 128 + h * 32 + kD4 * 4);
            }
            {
                int u = nt2 + (kKey1 >> 5), v = kKey1 & 31;
                long krow = ((long)b * 128 + rhs_s[u]) * 128 + rws_s[v];
                pkB = *(const float4*)(g_K + krow * 128 + h * 32 + kD4 * 4);
            }
            int k0 = 2 * vKp, k1 = 2 * vKp + 1;
            long row0 = ((long)b * 128 + rhs_s[nt2 + (k0 >> 5)]) * 128 + rws_s[k0 & 31];
            long row1 = ((long)b * 128 + rhs_s[nt2 + (k1 >> 5)]) * 128 + rws_s[k1 & 31];
            pvA = *(const float4*)(g_V + row0 * 128 + h * 32 + vD4 * 4);
            pvB = *(const float4*)(g_V + row1 * 128 + h * 32 + vD4 * 4);
        }

        const uint32_t* Khi_s  = KhiB  + buf * 64 * KST;
        const uint32_t* Klo_s  = KloB  + buf * 64 * KST;
        const uint32_t* Vthi_s = VthiB + buf * 32 * KST;
        const uint32_t* Vtlo_s = VtloB + buf * 32 * KST;

        // ---- compute on current buffer ----
        #pragma unroll 1
        for (int nb = 0; nb < 4; nb++) {
            uint32_t KHf[2][2][2], KLf[2][2][2];
            #pragma unroll
            for (int j2 = 0; j2 < 2; j2++) {
                int key = (2 * nb + j2) * 8 + g;
                #pragma unroll
                for (int kc = 0; kc < 2; kc++) {
                    KHf[j2][kc][0] = Khi_s[key * KST + kc * 8 + tg];
                    KHf[j2][kc][1] = Khi_s[key * KST + kc * 8 + 4 + tg];
                    KLf[j2][kc][0] = Klo_s[key * KST + kc * 8 + tg];
                    KLf[j2][kc][1] = Klo_s[key * KST + kc * 8 + 4 + tg];
                }
            }
            uint32_t VHf[4][2], VLf[4][2];
            #pragma unroll
            for (int nd = 0; nd < 4; nd++) {
                int d = nd * 8 + g;
                VHf[nd][0] = Vthi_s[d * KST + nb * 8 + tg];
                VHf[nd][1] = Vthi_s[d * KST + nb * 8 + 4 + tg];
                VLf[nd][0] = Vtlo_s[d * KST + nb * 8 + tg];
                VLf[nd][1] = Vtlo_s[d * KST + nb * 8 + 4 + tg];
            }
            #pragma unroll
            for (int mb = 0; mb < 2; mb++) {
                float S0[4] = {0.f, 0.f, 0.f, 0.f};
                float S1[4] = {0.f, 0.f, 0.f, 0.f};
                #pragma unroll
                for (int kc = 0; kc < 2; kc++) {
                    mma_bf16(S0, QH[mb][kc], KHf[0][kc]);
                    mma_bf16(S0, QL[mb][kc], KHf[0][kc]);
                    mma_bf16(S0, QH[mb][kc], KLf[0][kc]);
                    mma_bf16(S1, QH[mb][kc], KHf[1][kc]);
                    mma_bf16(S1, QL[mb][kc], KHf[1][kc]);
                    mma_bf16(S1, QH[mb][kc], KLf[1][kc]);
                }
                int kg0 = tile * 64 + nb * 16 + tg * 2;
                int kg8 = kg0 + 8;
                int rb0 = qbase[mb];
                int rb8 = rb0 + 8;
                float p0 = ex2f(S0[0] + bias_s[bidx(rb0, kg0)]);
                float p1 = ex2f(S0[1] + bias_s[bidx(rb0, kg0 + 1)]);
                float p2 = ex2f(S0[2] + bias_s[bidx(rb8, kg0)]);
                float p3 = ex2f(S0[3] + bias_s[bidx(rb8, kg0 + 1)]);
                float p4 = ex2f(S1[0] + bias_s[bidx(rb0, kg8)]);
                float p5 = ex2f(S1[1] + bias_s[bidx(rb0, kg8 + 1)]);
                float p6 = ex2f(S1[2] + bias_s[bidx(rb8, kg8)]);
                float p7 = ex2f(S1[3] + bias_s[bidx(rb8, kg8 + 1)]);
                ls[mb * 2 + 0] += (p0 + p1) + (p4 + p5);
                ls[mb * 2 + 1] += (p2 + p3) + (p6 + p7);
                uint32_t PH[4], PL[4];
                PH[0] = bfsplit(p0, p1, PL[0]);
                PH[1] = bfsplit(p2, p3, PL[1]);
                PH[2] = bfsplit(p4, p5, PL[2]);
                PH[3] = bfsplit(p6, p7, PL[3]);
                #pragma unroll
                for (int nd = 0; nd < 4; nd++) {
                    mma_bf16(Of[mb][nd], PH, VHf[nd]);
                    mma_bf16(Of[mb][nd], PL, VHf[nd]);
                    mma_bf16(Of[mb][nd], PH, VLf[nd]);
                }
            }
        }

        // ---- write prefetched tile into the other buffer ----
        if (pf) {
            uint32_t* Kh = KhiB  + nbuf * 64 * KST;
            uint32_t* Kl = KloB  + nbuf * 64 * KST;
            uint32_t* Vh = VthiB + nbuf * 32 * KST;
            uint32_t* Vl = VtloB + nbuf * 32 * KST;
            {
                uint32_t l01, l23;
                uint32_t h01 = bfsplit(pkA.x, pkA.y, l01);
                uint32_t h23 = bfsplit(pkA.z, pkA.w, l23);
                Kh[kKey0 * KST + kD4 * 2]     = h01;
                Kh[kKey0 * KST + kD4 * 2 + 1] = h23;
                Kl[kKey0 * KST + kD4 * 2]     = l01;
                Kl[kKey0 * KST + kD4 * 2 + 1] = l23;
                h01 = bfsplit(pkB.x, pkB.y, l01);
                h23 = bfsplit(pkB.z, pkB.w, l23);
                Kh[kKey1 * KST + kD4 * 2]     = h01;
                Kh[kKey1 * KST + kD4 * 2 + 1] = h23;
                Kl[kKey1 * KST + kD4 * 2]     = l01;
                Kl[kKey1 * KST + kD4 * 2 + 1] = l23;
            }
            const float* av = (const float*)&pvA;
            const float* cv = (const float*)&pvB;
            #pragma unroll
            for (int i = 0; i < 4; i++) {
                int d = vD4 * 4 + i;
                uint32_t lo;
                Vh[d * KST + vKp] = bfsplit(av[i], cv[i], lo);
                Vl[d * KST + vKp] = lo;
            }
        }
        __syncthreads();
    }

    // ---- finalize ----
    #pragma unroll
    for (int i = 0; i < 4; i++) {
        ls[i] += __shfl_xor_sync(0xffffffffu, ls[i], 1);
        ls[i] += __shfl_xor_sync(0xffffffffu, ls[i], 2);
        ls[i] = 1.f / ls[i];
    }
    #pragma unroll
    for (int mb = 0; mb < 2; mb++) {
        int r0 = wid * 32 + mb * 16 + g;
        int ii0 = r0 >> 4,        jj0 = r0 & 15;
        int ii1 = (r0 + 8) >> 4,  jj1 = (r0 + 8) & 15;
        float* o0 = g_AO + (((long)b * 128 + wi * 16 + ii0) * 128 + wj * 16 + jj0) * 128 + h * 32;
        float* o1 = g_AO + (((long)b * 128 + wi * 16 + ii1) * 128 + wj * 16 + jj1) * 128 + h * 32;
        float invlo = ls[mb * 2 + 0];
        float invhi = ls[mb * 2 + 1];
        #pragma unroll
        for (int nd = 0; nd < 4; nd++) {
            float2 v;
            v.x = Of[mb][nd][0] * invlo; v.y = Of[mb][nd][1] * invlo;
            *(float2*)(o0 + nd * 8 + tg * 2) = v;
            v.x = Of[mb][nd][2] * invhi; v.y = Of[mb][nd][3] * invhi;
            *(float2*)(o1 + nd * 8 + tg * 2) = v;
        }
    }
}

// ---------------------------------------------------------------------------
extern "C" void kernel_launch(void* const* d_in, const int* in_sizes, int n_in,
                              void* d_out, int out_size)
{
    const float* x  = (const float*)d_in[0];
    const float* Wq = (const float*)d_in[1];
    const float* bq = (const float*)d_in[2];
    const float* Wk = (const float*)d_in[3];
    const float* bk = (const float*)d_in[4];
    const float* Wv = (const float*)d_in[5];
    const float* bv = (const float*)d_in[6];
    const float* Wp = (const float*)d_in[7];
    const float* bp = (const float*)d_in[8];
    const float* bt = (const float*)d_in[9];
    const int* shift = (const int*)d_in[10];
    float* out = (float*)d_out;

    cudaFuncSetAttribute(proj_qkv_kernel, cudaFuncAttributeMaxDynamicSharedMemorySize, PROJ_SMEM);
    cudaFuncSetAttribute(out_proj_kernel, cudaFuncAttributeMaxDynamicSharedMemorySize, PROJ_SMEM);
    cudaFuncSetAttribute(attn_kernel,     cudaFuncAttributeMaxDynamicSharedMemorySize, ATTN_SMEM);

    proj_qkv_kernel<<<512, 256, PROJ_SMEM>>>(x, Wq, bq, Wk, bk, Wv, bv, shift);
    attn_kernel    <<<dim3(128, 4), 256, ATTN_SMEM>>>(bt);
    out_proj_kernel<<<512, 256, PROJ_SMEM>>>(Wp, bp, shift, out);
}